// round 12
// baseline (speedup 1.0000x reference)
#include <cuda_runtime.h>
#include <cuda_fp16.h>
#include <math.h>

#define BATCH 16
#define SEQ   1024
#define DM    512
#define NH    8
#define HD    64
#define NB    (NH*BATCH)

#define A_LD  40    // proj A tile pitch (halves)
#define B_LD  136   // proj B tile pitch (halves), 128+8
#define T_LD  72    // attn Q/K/V tile pitch (halves)

// Scratch, fp16 (device globals: allocation-free per harness rules).
__device__ __half g_Q[(size_t)NB*SEQ*HD];   // pre-scaled by 0.125
__device__ __half g_K[(size_t)NB*SEQ*HD];
__device__ __half g_V[(size_t)NB*SEQ*HD];
__device__ __half g_A[(size_t)NB*SEQ*HD];
__device__ __half g_xh[(size_t)BATCH*SEQ*DM];   // fp16 copy of x
__device__ __half g_wh[4][(size_t)DM*DM];       // fp16 wq,wk,wv,wo

__device__ __forceinline__ void st_h4(__half* p, float4 v) {
    __half2 lo = __floats2half2_rn(v.x, v.y);
    __half2 hi = __floats2half2_rn(v.z, v.w);
    uint2 u;
    u.x = *(unsigned int*)&lo;
    u.y = *(unsigned int*)&hi;
    *(uint2*)p = u;
}
__device__ __forceinline__ unsigned h2u(float a, float b) {
    __half2 h = __floats2half2_rn(a, b);
    return *(unsigned*)&h;
}

// ---------------------------------------------------------------------------
// PTX mma/ldmatrix helpers
// ---------------------------------------------------------------------------
__device__ __forceinline__ unsigned su(const void* p) {
    return (unsigned)__cvta_generic_to_shared(p);
}
__device__ __forceinline__ void ldsm4(unsigned& r0, unsigned& r1,
                                      unsigned& r2, unsigned& r3, unsigned a) {
    asm volatile("ldmatrix.sync.aligned.m8n8.x4.shared.b16 {%0,%1,%2,%3},[%4];"
                 : "=r"(r0), "=r"(r1), "=r"(r2), "=r"(r3) : "r"(a));
}
__device__ __forceinline__ void ldsm4t(unsigned& r0, unsigned& r1,
                                       unsigned& r2, unsigned& r3, unsigned a) {
    asm volatile("ldmatrix.sync.aligned.m8n8.x4.trans.shared.b16 {%0,%1,%2,%3},[%4];"
                 : "=r"(r0), "=r"(r1), "=r"(r2), "=r"(r3) : "r"(a));
}
__device__ __forceinline__ void mma_f16(float* d, const unsigned* a,
                                        const unsigned* b) {
    asm volatile("mma.sync.aligned.m16n8k16.row.col.f32.f16.f16.f32 "
                 "{%0,%1,%2,%3},{%4,%5,%6,%7},{%8,%9},{%0,%1,%2,%3};"
                 : "+f"(d[0]), "+f"(d[1]), "+f"(d[2]), "+f"(d[3])
                 : "r"(a[0]), "r"(a[1]), "r"(a[2]), "r"(a[3]),
                   "r"(b[0]), "r"(b[1]));
}

// ---------------------------------------------------------------------------
// fp32 -> fp16 conversion prep kernels
// ---------------------------------------------------------------------------
__global__ __launch_bounds__(256) void cvt_kernel(const float* __restrict__ src,
                                                  __half* __restrict__ dst, int n) {
    int i = (blockIdx.x * 256 + threadIdx.x) * 4;
    if (i < n) st_h4(dst + i, *(const float4*)(src + i));
}
__global__ __launch_bounds__(256) void cvt_w_kernel(
    const float* __restrict__ wq, const float* __restrict__ wk,
    const float* __restrict__ wv, const float* __restrict__ wo) {
    const float* src = (blockIdx.y == 0) ? wq : (blockIdx.y == 1) ? wk
                     : (blockIdx.y == 2) ? wv : wo;
    __half* dst = g_wh[blockIdx.y];
    int i = (blockIdx.x * 256 + threadIdx.x) * 4;
    st_h4(dst + i, *(const float4*)(src + i));
}

// ---------------------------------------------------------------------------
// QKV projection (unchanged from R11): PTX mma, double-buffered smem.
// ---------------------------------------------------------------------------
__global__ __launch_bounds__(256, 2) void proj_qkv_kernel(
    const float* __restrict__ bq, const float* __restrict__ bk,
    const float* __restrict__ bv)
{
    __shared__ __half As[2][128*A_LD];
    __shared__ __half Bs[2][32*B_LD];

    const float* bias; __half* dst; float oscale;
    const __half* w = g_wh[blockIdx.z];
    if (blockIdx.z == 0)      { bias = bq; dst = g_Q; oscale = 0.125f; }
    else if (blockIdx.z == 1) { bias = bk; dst = g_K; oscale = 1.f; }
    else                      { bias = bv; dst = g_V; oscale = 1.f; }

    const int m0 = blockIdx.x * 128;
    const int n0 = blockIdx.y * 128;
    const int tid = threadIdx.x;
    const int wid = tid >> 5, lane = tid & 31;
    const int wm = wid >> 1, wn = wid & 1;
    const int quad = lane >> 2, lane4 = lane & 3;
    const int sub = lane >> 3, lr8 = lane & 7;
    const int a_r = (sub & 1)*8 + lr8, a_c = (sub >> 1)*8;

    const int ar = tid >> 3, ac = (tid & 7) * 4;
    const int br = tid >> 5, bc = (tid & 31) * 4;

    float o[2][8][4];
    #pragma unroll
    for (int i = 0; i < 2; i++)
        #pragma unroll
        for (int j = 0; j < 8; j++)
            #pragma unroll
            for (int e = 0; e < 4; e++) o[i][j][e] = 0.f;

    float2 bias2[8];
    #pragma unroll
    for (int nf = 0; nf < 8; nf++)
        bias2[nf] = *(const float2*)(bias + n0 + wn*64 + nf*8 + lane4*2);

    uint2 ra[4], rb[4];
    #pragma unroll
    for (int it = 0; it < 4; it++)
        ra[it] = *(const uint2*)(g_xh + (size_t)(m0 + ar + it*32)*DM + ac);
    #pragma unroll
    for (int it = 0; it < 4; it++)
        rb[it] = *(const uint2*)(w + (size_t)(br + it*8)*DM + n0 + bc);

    const unsigned ab[2] = {su(As[0]), su(As[1])};
    const unsigned bb[2] = {su(Bs[0]), su(Bs[1])};

    for (int kt = 0; kt < 16; kt++) {
        const int cb = kt & 1;
        #pragma unroll
        for (int it = 0; it < 4; it++)
            *(uint2*)(As[cb] + (ar + it*32)*A_LD + ac) = ra[it];
        #pragma unroll
        for (int it = 0; it < 4; it++)
            *(uint2*)(Bs[cb] + (br + it*8)*B_LD + bc) = rb[it];
        __syncthreads();

        if (kt < 15) {
            int k0 = (kt + 1) * 32;
            #pragma unroll
            for (int it = 0; it < 4; it++)
                ra[it] = *(const uint2*)(g_xh + (size_t)(m0 + ar + it*32)*DM + k0 + ac);
            #pragma unroll
            for (int it = 0; it < 4; it++)
                rb[it] = *(const uint2*)(w + (size_t)(k0 + br + it*8)*DM + n0 + bc);
        }

        #pragma unroll
        for (int kf = 0; kf < 2; kf++) {
            unsigned a[2][4], b[8][2];
            #pragma unroll
            for (int mf = 0; mf < 2; mf++)
                ldsm4(a[mf][0], a[mf][1], a[mf][2], a[mf][3],
                      ab[cb] + ((wm*32 + mf*16 + a_r)*A_LD + kf*16 + a_c)*2);
            #pragma unroll
            for (int nb = 0; nb < 4; nb++) {
                unsigned r0, r1, r2, r3;
                ldsm4t(r0, r1, r2, r3,
                       bb[cb] + ((kf*16 + (sub & 1)*8 + lr8)*B_LD
                                 + wn*64 + nb*16 + (sub >> 1)*8)*2);
                b[nb*2+0][0] = r0; b[nb*2+0][1] = r1;
                b[nb*2+1][0] = r2; b[nb*2+1][1] = r3;
            }
            #pragma unroll
            for (int mf = 0; mf < 2; mf++)
                #pragma unroll
                for (int nf = 0; nf < 8; nf++)
                    mma_f16(o[mf][nf], a[mf], b[nf]);
        }
    }

    #pragma unroll
    for (int mf = 0; mf < 2; mf++) {
        int row0 = m0 + wm*32 + mf*16 + quad;
        int b0 = row0 >> 10, s0 = row0 & 1023;
        int row1 = row0 + 8;
        int b1 = row1 >> 10, s1 = row1 & 1023;
        #pragma unroll
        for (int nf = 0; nf < 8; nf++) {
            int col = n0 + wn*64 + nf*8 + lane4*2;
            int h = col >> 6, q0 = col & 63;
            *(__half2*)(dst + (((size_t)(h*BATCH + b0))*SEQ + s0)*HD + q0) =
                __floats2half2_rn((o[mf][nf][0] + bias2[nf].x) * oscale,
                                  (o[mf][nf][1] + bias2[nf].y) * oscale);
            *(__half2*)(dst + (((size_t)(h*BATCH + b1))*SEQ + s1)*HD + q0) =
                __floats2half2_rn((o[mf][nf][2] + bias2[nf].x) * oscale,
                                  (o[mf][nf][3] + bias2[nf].y) * oscale);
        }
    }
}

// ---------------------------------------------------------------------------
// Fused attention: P kept in registers (S acc fragments == PV A fragments).
// 8 warps = 4(M) x 2(key-half). Warp: rows wm*32, keys wn*32, ALL 64 out cols.
// Partial O (per key-half) reduced across wn pairs in the epilogue via smem.
// 2 syncs/iter, no P smem traffic.
// ---------------------------------------------------------------------------
#define QT_ROWS 128
#define ATTN_SMEM (128*T_LD*2 + 2*64*T_LD*2 + 1024*4 + 2*128*4)

__global__ __launch_bounds__(256, 2) void attn_kernel(const int* __restrict__ pmask,
                                                      float* __restrict__ raw)
{
    extern __shared__ char shb[];
    __half* Qs = (__half*)shb;                 // [128][72]
    __half* Ks = Qs + 128*T_LD;                // [64][72]
    __half* Vs = Ks + 64*T_LD;                 // [64][72]
    float*  mm = (float*)(Vs + 64*T_LD);       // [1024]
    float*  ls = mm + 1024;                    // [2][128]
    float*  ob = (float*)shb;                  // [128][64] epilogue alias (32KB)

    const int n  = blockIdx.y;
    const int qt = blockIdx.x;
    const int tid = threadIdx.x;
    const int wid = tid >> 5, lane = tid & 31;
    const int wm = wid >> 1, wn = wid & 1;
    const int quad = lane >> 2, lane4 = lane & 3;
    const int sub = lane >> 3, lr8 = lane & 7;
    const int mb = n >> 3;                     // faithful mask-index mismatch

    const int a_r = (sub & 1)*8 + lr8, a_c = (sub >> 1)*8;
    const int b_r = (sub >> 1)*8 + lr8, b_c = (sub & 1)*8;

    const __half* qsrc = g_Q + ((size_t)n*SEQ + qt*128)*HD;
    #pragma unroll
    for (int it = 0; it < 8; it++) {
        int idx = tid + it*256;
        int r = idx >> 4, d0 = (idx & 15) * 4;
        *(uint2*)(Qs + r*T_LD + d0) = *(const uint2*)(qsrc + r*HD + d0);
    }
    {
        int4 m4 = *(const int4*)(pmask + (size_t)mb*SEQ + tid*4);
        float4 f4;
        f4.x = m4.x ? 1.f : 0.f; f4.y = m4.y ? 1.f : 0.f;
        f4.z = m4.z ? 1.f : 0.f; f4.w = m4.w ? 1.f : 0.f;
        *(float4*)(mm + tid*4) = f4;
    }

    const __half* ksrc = g_K + (size_t)n*SEQ*HD;
    const __half* vsrc = g_V + (size_t)n*SEQ*HD;
    const int lr = tid >> 4, ld0 = (tid & 15) * 4;

    float o[2][8][4];       // [mf][out-col frag][c]; partial over warp's keys
    #pragma unroll
    for (int i = 0; i < 2; i++)
        #pragma unroll
        for (int j = 0; j < 8; j++)
            #pragma unroll
            for (int e = 0; e < 4; e++) o[i][j][e] = 0.f;
    float rs[2][2] = {{0.f, 0.f}, {0.f, 0.f}};

    uint2 rk[4], rv[4];
    #pragma unroll
    for (int it = 0; it < 4; it++) {
        int t = lr + it*16;
        rk[it] = *(const uint2*)(ksrc + (size_t)t*HD + ld0);
        rv[it] = *(const uint2*)(vsrc + (size_t)t*HD + ld0);
    }

    const unsigned qb = su(Qs), kb = su(Ks), vb = su(Vs);
    const size_t rowg = (size_t)n*SEQ + (size_t)qt*128;

    for (int kt = 0; kt < 16; ++kt) {
        __syncthreads();   // prior iter's K/V reads complete
        #pragma unroll
        for (int it = 0; it < 4; it++) {
            int t = lr + it*16;
            *(uint2*)(Ks + t*T_LD + ld0) = rk[it];
            *(uint2*)(Vs + t*T_LD + ld0) = rv[it];
        }
        __syncthreads();

        // ---- S = (Q/8) K^T : warp 32 rows x 32 keys ----
        float s[2][4][4];
        #pragma unroll
        for (int i = 0; i < 2; i++)
            #pragma unroll
            for (int j = 0; j < 4; j++)
                #pragma unroll
                for (int e = 0; e < 4; e++) s[i][j][e] = 0.f;

        #pragma unroll
        for (int kf = 0; kf < 4; kf++) {
            unsigned a[2][4], b[4][2];
            #pragma unroll
            for (int mf = 0; mf < 2; mf++)
                ldsm4(a[mf][0], a[mf][1], a[mf][2], a[mf][3],
                      qb + ((wm*32 + mf*16 + a_r)*T_LD + kf*16 + a_c)*2);
            #pragma unroll
            for (int nb = 0; nb < 2; nb++) {
                unsigned r0, r1, r2, r3;
                ldsm4(r0, r1, r2, r3,
                      kb + ((wn*32 + nb*16 + b_r)*T_LD + kf*16 + b_c)*2);
                b[nb*2+0][0] = r0; b[nb*2+0][1] = r1;
                b[nb*2+1][0] = r2; b[nb*2+1][1] = r3;
            }
            #pragma unroll
            for (int mf = 0; mf < 2; mf++)
                #pragma unroll
                for (int nf = 0; nf < 4; nf++)
                    mma_f16(s[mf][nf], a[mf], b[nf]);
        }

        // ---- raw write + mask + exp, packed into PV A-fragments (regs) ----
        unsigned ph[2][4][2];
        #pragma unroll
        for (int mf = 0; mf < 2; mf++) {
            int r0 = wm*32 + mf*16 + quad;
            #pragma unroll
            for (int nf = 0; nf < 4; nf++) {
                int lcol = wn*32 + nf*8 + lane4*2;
                int col  = kt*64 + lcol;
                __stcs((float2*)(raw + (rowg + r0)*SEQ + col),
                       make_float2(s[mf][nf][0], s[mf][nf][1]));
                __stcs((float2*)(raw + (rowg + r0 + 8)*SEQ + col),
                       make_float2(s[mf][nf][2], s[mf][nf][3]));
                float2 m2 = *(const float2*)(mm + col);
                float p00 = m2.x * __expf(s[mf][nf][0]);
                float p01 = m2.y * __expf(s[mf][nf][1]);
                float p10 = m2.x * __expf(s[mf][nf][2]);
                float p11 = m2.y * __expf(s[mf][nf][3]);
                rs[mf][0] += p00 + p01;
                rs[mf][1] += p10 + p11;
                ph[mf][nf][0] = h2u(p00, p01);   // rows quad,   k lo
                ph[mf][nf][1] = h2u(p10, p11);   // rows quad+8, k lo
            }
        }

        if (kt < 15) {     // prefetch next K/V; overlaps PV mma
            #pragma unroll
            for (int it = 0; it < 4; it++) {
                int t = (kt+1)*64 + lr + it*16;
                rk[it] = *(const uint2*)(ksrc + (size_t)t*HD + ld0);
                rv[it] = *(const uint2*)(vsrc + (size_t)t*HD + ld0);
            }
        }

        // ---- O += P @ V over warp's own 32 keys, all 64 out cols ----
        #pragma unroll
        for (int tf = 0; tf < 2; tf++) {
            unsigned a[2][4], b[8][2];
            #pragma unroll
            for (int mf = 0; mf < 2; mf++) {
                a[mf][0] = ph[mf][2*tf+0][0];
                a[mf][1] = ph[mf][2*tf+0][1];
                a[mf][2] = ph[mf][2*tf+1][0];
                a[mf][3] = ph[mf][2*tf+1][1];
            }
            #pragma unroll
            for (int nb = 0; nb < 4; nb++) {
                unsigned r0, r1, r2, r3;
                ldsm4t(r0, r1, r2, r3,
                       vb + ((wn*32 + tf*16 + (sub & 1)*8 + lr8)*T_LD
                             + nb*16 + (sub >> 1)*8)*2);
                b[nb*2+0][0] = r0; b[nb*2+0][1] = r1;
                b[nb*2+1][0] = r2; b[nb*2+1][1] = r3;
            }
            #pragma unroll
            for (int mf = 0; mf < 2; mf++)
                #pragma unroll
                for (int nf = 0; nf < 8; nf++)
                    mma_f16(o[mf][nf], a[mf], b[nf]);
        }
    }

    // ---- row-sum reduce (lane4 shfl, cross-wn via ls) ----
    #pragma unroll
    for (int mf = 0; mf < 2; mf++)
        #pragma unroll
        for (int rg = 0; rg < 2; rg++) {
            rs[mf][rg] += __shfl_xor_sync(0xffffffffu, rs[mf][rg], 1);
            rs[mf][rg] += __shfl_xor_sync(0xffffffffu, rs[mf][rg], 2);
        }

    __syncthreads();   // all V reads done; safe to alias ob over Q/K/V tiles
    if (lane4 == 0) {
        #pragma unroll
        for (int mf = 0; mf < 2; mf++) {
            int r0 = wm*32 + mf*16 + quad;
            ls[wn*128 + r0]     = rs[mf][0];
            ls[wn*128 + r0 + 8] = rs[mf][1];
        }
    }
    if (wn == 1) {     // stash key-half-1 partial O
        #pragma unroll
        for (int mf = 0; mf < 2; mf++) {
            int r0 = wm*32 + mf*16 + quad;
            #pragma unroll
            for (int nf = 0; nf < 8; nf++) {
                int col = nf*8 + lane4*2;
                *(float2*)(ob + r0*64 + col)     = make_float2(o[mf][nf][0], o[mf][nf][1]);
                *(float2*)(ob + (r0+8)*64 + col) = make_float2(o[mf][nf][2], o[mf][nf][3]);
            }
        }
    }
    __syncthreads();

    if (wn == 0) {     // combine halves, normalize, store fp16
        #pragma unroll
        for (int mf = 0; mf < 2; mf++) {
            int r0 = wm*32 + mf*16 + quad;
            float inv0 = 1.f / (ls[r0] + ls[128 + r0]);
            float inv1 = 1.f / (ls[r0 + 8] + ls[128 + r0 + 8]);
            __half* adst = g_A + (rowg + r0)*HD;
            #pragma unroll
            for (int nf = 0; nf < 8; nf++) {
                int col = nf*8 + lane4*2;
                float2 p0 = *(const float2*)(ob + r0*64 + col);
                float2 p1 = *(const float2*)(ob + (r0+8)*64 + col);
                *(__half2*)(adst + col) =
                    __floats2half2_rn((o[mf][nf][0] + p0.x)*inv0,
                                      (o[mf][nf][1] + p0.y)*inv0);
                *(__half2*)(adst + 8*HD + col) =
                    __floats2half2_rn((o[mf][nf][2] + p1.x)*inv1,
                                      (o[mf][nf][3] + p1.y)*inv1);
            }
        }
    }
}

// ---------------------------------------------------------------------------
// Output projection (unchanged from R11).
// ---------------------------------------------------------------------------
__global__ __launch_bounds__(256, 2) void proj_out_kernel(
    const float* __restrict__ bo, float* __restrict__ out)
{
    __shared__ __half As[2][128*A_LD];
    __shared__ __half Bs[2][32*B_LD];

    const __half* w = g_wh[3];
    const int m0 = blockIdx.x * 128;
    const int n0 = blockIdx.y * 128;
    const int tid = threadIdx.x;
    const int wid = tid >> 5, lane = tid & 31;
    const int wm = wid >> 1, wn = wid & 1;
    const int quad = lane >> 2, lane4 = lane & 3;
    const int sub = lane >> 3, lr8 = lane & 7;
    const int a_r = (sub & 1)*8 + lr8, a_c = (sub >> 1)*8;

    const int ar = tid >> 3, ac = (tid & 7) * 4;
    const int br = tid >> 5, bc = (tid & 31) * 4;
    const int rowA0 = m0 + ar;

    float o[2][8][4];
    #pragma unroll
    for (int i = 0; i < 2; i++)
        #pragma unroll
        for (int j = 0; j < 8; j++)
            #pragma unroll
            for (int e = 0; e < 4; e++) o[i][j][e] = 0.f;

    float2 bias2[8];
    #pragma unroll
    for (int nf = 0; nf < 8; nf++)
        bias2[nf] = *(const float2*)(bo + n0 + wn*64 + nf*8 + lane4*2);

    uint2 ra[4], rb[4];
    #pragma unroll
    for (int it = 0; it < 4; it++) {
        int row = rowA0 + it*32;
        int b = row >> 10, s = row & 1023;
        ra[it] = *(const uint2*)(g_A + ((size_t)b*SEQ + s)*HD + ac);
    }
    #pragma unroll
    for (int it = 0; it < 4; it++)
        rb[it] = *(const uint2*)(w + (size_t)(br + it*8)*DM + n0 + bc);

    const unsigned ab[2] = {su(As[0]), su(As[1])};
    const unsigned bb[2] = {su(Bs[0]), su(Bs[1])};

    for (int kt = 0; kt < 16; kt++) {
        const int cb = kt & 1;
        #pragma unroll
        for (int it = 0; it < 4; it++)
            *(uint2*)(As[cb] + (ar + it*32)*A_LD + ac) = ra[it];
        #pragma unroll
        for (int it = 0; it < 4; it++)
            *(uint2*)(Bs[cb] + (br + it*8)*B_LD + bc) = rb[it];
        __syncthreads();

        if (kt < 15) {
            int k0 = (kt + 1) * 32;
            int h = k0 >> 6, v0 = k0 & 63;
            #pragma unroll
            for (int it = 0; it < 4; it++) {
                int row = rowA0 + it*32;
                int b = row >> 10, s = row & 1023;
                ra[it] = *(const uint2*)(g_A + (((size_t)(h*BATCH + b))*SEQ + s)*HD + v0 + ac);
            }
            #pragma unroll
            for (int it = 0; it < 4; it++)
                rb[it] = *(const uint2*)(w + (size_t)(k0 + br + it*8)*DM + n0 + bc);
        }

        #pragma unroll
        for (int kf = 0; kf < 2; kf++) {
            unsigned a[2][4], b[8][2];
            #pragma unroll
            for (int mf = 0; mf < 2; mf++)
                ldsm4(a[mf][0], a[mf][1], a[mf][2], a[mf][3],
                      ab[cb] + ((wm*32 + mf*16 + a_r)*A_LD + kf*16 + a_c)*2);
            #pragma unroll
            for (int nb = 0; nb < 4; nb++) {
                unsigned r0, r1, r2, r3;
                ldsm4t(r0, r1, r2, r3,
                       bb[cb] + ((kf*16 + (sub & 1)*8 + lr8)*B_LD
                                 + wn*64 + nb*16 + (sub >> 1)*8)*2);
                b[nb*2+0][0] = r0; b[nb*2+0][1] = r1;
                b[nb*2+1][0] = r2; b[nb*2+1][1] = r3;
            }
            #pragma unroll
            for (int mf = 0; mf < 2; mf++)
                #pragma unroll
                for (int nf = 0; nf < 8; nf++)
                    mma_f16(o[mf][nf], a[mf], b[nf]);
        }
    }

    #pragma unroll
    for (int mf = 0; mf < 2; mf++) {
        int row0 = m0 + wm*32 + mf*16 + quad;
        #pragma unroll
        for (int nf = 0; nf < 8; nf++) {
            int col = n0 + wn*64 + nf*8 + lane4*2;
            __stcs((float2*)(out + (size_t)row0*DM + col),
                   make_float2(o[mf][nf][0] + bias2[nf].x,
                               o[mf][nf][1] + bias2[nf].y));
            __stcs((float2*)(out + (size_t)(row0+8)*DM + col),
                   make_float2(o[mf][nf][2] + bias2[nf].x,
                               o[mf][nf][3] + bias2[nf].y));
        }
    }
}

// ---------------------------------------------------------------------------
extern "C" void kernel_launch(void* const* d_in, const int* in_sizes, int n_in,
                              void* d_out, int out_size)
{
    (void)in_sizes; (void)n_in; (void)out_size;
    const float* x  = (const float*)d_in[0];
    const int*   pm = (const int*)  d_in[1];
    const float* wq = (const float*)d_in[2];
    const float* bq = (const float*)d_in[3];
    const float* wk = (const float*)d_in[4];
    const float* bk = (const float*)d_in[5];
    const float* wv = (const float*)d_in[6];
    const float* bv = (const float*)d_in[7];
    const float* wo = (const float*)d_in[8];
    const float* bo = (const float*)d_in[9];

    float* out = (float*)d_out;
    float* raw = out + (size_t)BATCH*SEQ*DM;

    cudaFuncSetAttribute(attn_kernel, cudaFuncAttributeMaxDynamicSharedMemorySize,
                         ATTN_SMEM);

    __half* xh;
    cudaGetSymbolAddress((void**)&xh, g_xh);

    const int NX = BATCH*SEQ*DM, NW = DM*DM;
    cvt_kernel<<<NX/1024, 256>>>(x, xh, NX);
    cvt_w_kernel<<<dim3(NW/1024, 4), 256>>>(wq, wk, wv, wo);

    proj_qkv_kernel<<<dim3(BATCH*SEQ/128, DM/128, 3), 256>>>(bq, bk, bv);
    attn_kernel<<<dim3(SEQ/QT_ROWS, NB), 256, ATTN_SMEM>>>(pm, raw);
    proj_out_kernel<<<dim3(BATCH*SEQ/128, DM/128), 256>>>(bo, out);
}

// round 13
// speedup vs baseline: 1.0755x; 1.0755x over previous
#include <cuda_runtime.h>
#include <cuda_fp16.h>
#include <math.h>

#define BATCH 16
#define SEQ   1024
#define DM    512
#define NH    8
#define HD    64
#define NB    (NH*BATCH)

#define A_LD  40    // proj A tile pitch (halves)
#define B_LD  136   // proj B tile pitch (halves), 128+8
#define T_LD  72    // attn Q/K/V tile pitch (halves)

// Scratch, fp16 (device globals: allocation-free per harness rules).
__device__ __half g_Q[(size_t)NB*SEQ*HD];   // pre-scaled by 0.125
__device__ __half g_K[(size_t)NB*SEQ*HD];
__device__ __half g_V[(size_t)NB*SEQ*HD];
__device__ __half g_A[(size_t)NB*SEQ*HD];
__device__ __half g_xh[(size_t)BATCH*SEQ*DM];   // fp16 copy of x
__device__ __half g_wh[4][(size_t)DM*DM];       // fp16 wq,wk,wv,wo

__device__ __forceinline__ void st_h4(__half* p, float4 v) {
    __half2 lo = __floats2half2_rn(v.x, v.y);
    __half2 hi = __floats2half2_rn(v.z, v.w);
    uint2 u;
    u.x = *(unsigned int*)&lo;
    u.y = *(unsigned int*)&hi;
    *(uint2*)p = u;
}
__device__ __forceinline__ unsigned h2u(float a, float b) {
    __half2 h = __floats2half2_rn(a, b);
    return *(unsigned*)&h;
}

// ---------------------------------------------------------------------------
// PTX mma/ldmatrix helpers
// ---------------------------------------------------------------------------
__device__ __forceinline__ unsigned su(const void* p) {
    return (unsigned)__cvta_generic_to_shared(p);
}
__device__ __forceinline__ void ldsm4(unsigned& r0, unsigned& r1,
                                      unsigned& r2, unsigned& r3, unsigned a) {
    asm volatile("ldmatrix.sync.aligned.m8n8.x4.shared.b16 {%0,%1,%2,%3},[%4];"
                 : "=r"(r0), "=r"(r1), "=r"(r2), "=r"(r3) : "r"(a));
}
__device__ __forceinline__ void ldsm4t(unsigned& r0, unsigned& r1,
                                       unsigned& r2, unsigned& r3, unsigned a) {
    asm volatile("ldmatrix.sync.aligned.m8n8.x4.trans.shared.b16 {%0,%1,%2,%3},[%4];"
                 : "=r"(r0), "=r"(r1), "=r"(r2), "=r"(r3) : "r"(a));
}
__device__ __forceinline__ void mma_f16(float* d, const unsigned* a,
                                        const unsigned* b) {
    asm volatile("mma.sync.aligned.m16n8k16.row.col.f32.f16.f16.f32 "
                 "{%0,%1,%2,%3},{%4,%5,%6,%7},{%8,%9},{%0,%1,%2,%3};"
                 : "+f"(d[0]), "+f"(d[1]), "+f"(d[2]), "+f"(d[3])
                 : "r"(a[0]), "r"(a[1]), "r"(a[2]), "r"(a[3]),
                   "r"(b[0]), "r"(b[1]));
}

// ---------------------------------------------------------------------------
// fp32 -> fp16 conversion prep kernels
// ---------------------------------------------------------------------------
__global__ __launch_bounds__(256) void cvt_kernel(const float* __restrict__ src,
                                                  __half* __restrict__ dst, int n) {
    int i = (blockIdx.x * 256 + threadIdx.x) * 4;
    if (i < n) st_h4(dst + i, *(const float4*)(src + i));
}
__global__ __launch_bounds__(256) void cvt_w_kernel(
    const float* __restrict__ wq, const float* __restrict__ wk,
    const float* __restrict__ wv, const float* __restrict__ wo) {
    const float* src = (blockIdx.y == 0) ? wq : (blockIdx.y == 1) ? wk
                     : (blockIdx.y == 2) ? wv : wo;
    __half* dst = g_wh[blockIdx.y];
    int i = (blockIdx.x * 256 + threadIdx.x) * 4;
    st_h4(dst + i, *(const float4*)(src + i));
}

// ---------------------------------------------------------------------------
// QKV projection (unchanged from R11): PTX mma, double-buffered smem.
// ---------------------------------------------------------------------------
__global__ __launch_bounds__(256, 2) void proj_qkv_kernel(
    const float* __restrict__ bq, const float* __restrict__ bk,
    const float* __restrict__ bv)
{
    __shared__ __half As[2][128*A_LD];
    __shared__ __half Bs[2][32*B_LD];

    const float* bias; __half* dst; float oscale;
    const __half* w = g_wh[blockIdx.z];
    if (blockIdx.z == 0)      { bias = bq; dst = g_Q; oscale = 0.125f; }
    else if (blockIdx.z == 1) { bias = bk; dst = g_K; oscale = 1.f; }
    else                      { bias = bv; dst = g_V; oscale = 1.f; }

    const int m0 = blockIdx.x * 128;
    const int n0 = blockIdx.y * 128;
    const int tid = threadIdx.x;
    const int wid = tid >> 5, lane = tid & 31;
    const int wm = wid >> 1, wn = wid & 1;
    const int quad = lane >> 2, lane4 = lane & 3;
    const int sub = lane >> 3, lr8 = lane & 7;
    const int a_r = (sub & 1)*8 + lr8, a_c = (sub >> 1)*8;

    const int ar = tid >> 3, ac = (tid & 7) * 4;
    const int br = tid >> 5, bc = (tid & 31) * 4;

    float o[2][8][4];
    #pragma unroll
    for (int i = 0; i < 2; i++)
        #pragma unroll
        for (int j = 0; j < 8; j++)
            #pragma unroll
            for (int e = 0; e < 4; e++) o[i][j][e] = 0.f;

    float2 bias2[8];
    #pragma unroll
    for (int nf = 0; nf < 8; nf++)
        bias2[nf] = *(const float2*)(bias + n0 + wn*64 + nf*8 + lane4*2);

    uint2 ra[4], rb[4];
    #pragma unroll
    for (int it = 0; it < 4; it++)
        ra[it] = *(const uint2*)(g_xh + (size_t)(m0 + ar + it*32)*DM + ac);
    #pragma unroll
    for (int it = 0; it < 4; it++)
        rb[it] = *(const uint2*)(w + (size_t)(br + it*8)*DM + n0 + bc);

    const unsigned ab[2] = {su(As[0]), su(As[1])};
    const unsigned bb[2] = {su(Bs[0]), su(Bs[1])};

    for (int kt = 0; kt < 16; kt++) {
        const int cb = kt & 1;
        #pragma unroll
        for (int it = 0; it < 4; it++)
            *(uint2*)(As[cb] + (ar + it*32)*A_LD + ac) = ra[it];
        #pragma unroll
        for (int it = 0; it < 4; it++)
            *(uint2*)(Bs[cb] + (br + it*8)*B_LD + bc) = rb[it];
        __syncthreads();

        if (kt < 15) {
            int k0 = (kt + 1) * 32;
            #pragma unroll
            for (int it = 0; it < 4; it++)
                ra[it] = *(const uint2*)(g_xh + (size_t)(m0 + ar + it*32)*DM + k0 + ac);
            #pragma unroll
            for (int it = 0; it < 4; it++)
                rb[it] = *(const uint2*)(w + (size_t)(k0 + br + it*8)*DM + n0 + bc);
        }

        #pragma unroll
        for (int kf = 0; kf < 2; kf++) {
            unsigned a[2][4], b[8][2];
            #pragma unroll
            for (int mf = 0; mf < 2; mf++)
                ldsm4(a[mf][0], a[mf][1], a[mf][2], a[mf][3],
                      ab[cb] + ((wm*32 + mf*16 + a_r)*A_LD + kf*16 + a_c)*2);
            #pragma unroll
            for (int nb = 0; nb < 4; nb++) {
                unsigned r0, r1, r2, r3;
                ldsm4t(r0, r1, r2, r3,
                       bb[cb] + ((kf*16 + (sub & 1)*8 + lr8)*B_LD
                                 + wn*64 + nb*16 + (sub >> 1)*8)*2);
                b[nb*2+0][0] = r0; b[nb*2+0][1] = r1;
                b[nb*2+1][0] = r2; b[nb*2+1][1] = r3;
            }
            #pragma unroll
            for (int mf = 0; mf < 2; mf++)
                #pragma unroll
                for (int nf = 0; nf < 8; nf++)
                    mma_f16(o[mf][nf], a[mf], b[nf]);
        }
    }

    #pragma unroll
    for (int mf = 0; mf < 2; mf++) {
        int row0 = m0 + wm*32 + mf*16 + quad;
        int b0 = row0 >> 10, s0 = row0 & 1023;
        int row1 = row0 + 8;
        int b1 = row1 >> 10, s1 = row1 & 1023;
        #pragma unroll
        for (int nf = 0; nf < 8; nf++) {
            int col = n0 + wn*64 + nf*8 + lane4*2;
            int h = col >> 6, q0 = col & 63;
            *(__half2*)(dst + (((size_t)(h*BATCH + b0))*SEQ + s0)*HD + q0) =
                __floats2half2_rn((o[mf][nf][0] + bias2[nf].x) * oscale,
                                  (o[mf][nf][1] + bias2[nf].y) * oscale);
            *(__half2*)(dst + (((size_t)(h*BATCH + b1))*SEQ + s1)*HD + q0) =
                __floats2half2_rn((o[mf][nf][2] + bias2[nf].x) * oscale,
                                  (o[mf][nf][3] + bias2[nf].y) * oscale);
        }
    }
}

// ---------------------------------------------------------------------------
// Fused attention: 64 q-rows/block, register-resident P (no P smem traffic).
// 8 warps = 4(M, 16 rows) x 2(key-half, 32 keys). Warp computes S for its
// 16 rows x 32 keys, packs exp into PV A-fragments, accumulates partial O
// (all 64 out cols) over its own keys. Key-half partials combined in epilogue.
// ---------------------------------------------------------------------------
#define QT_ROWS 64
#define ATTN_SMEM (3*64*T_LD*2 + 1024*4 + 2*64*4)

__global__ __launch_bounds__(256, 2) void attn_kernel(const int* __restrict__ pmask,
                                                      float* __restrict__ raw)
{
    extern __shared__ char shb[];
    __half* Qs = (__half*)shb;                 // [64][72]
    __half* Ks = Qs + 64*T_LD;                 // [64][72]
    __half* Vs = Ks + 64*T_LD;                 // [64][72]
    float*  mm = (float*)(Vs + 64*T_LD);       // [1024]
    float*  ls = mm + 1024;                    // [2][64]
    float*  ob = (float*)shb;                  // [64][64] epilogue alias (16KB over Qs/Ks)

    const int n  = blockIdx.y;
    const int qt = blockIdx.x;
    const int tid = threadIdx.x;
    const int wid = tid >> 5, lane = tid & 31;
    const int wm = wid >> 1, wn = wid & 1;     // wm: 16-row group; wn: key half
    const int quad = lane >> 2, lane4 = lane & 3;
    const int sub = lane >> 3, lr8 = lane & 7;
    const int mb = n >> 3;                     // faithful mask-index mismatch

    const int a_r = (sub & 1)*8 + lr8, a_c = (sub >> 1)*8;
    const int b_r = (sub >> 1)*8 + lr8, b_c = (sub & 1)*8;

    // Q tile 64x64 (pre-scaled fp16 copy)
    const __half* qsrc = g_Q + ((size_t)n*SEQ + qt*QT_ROWS)*HD;
    #pragma unroll
    for (int it = 0; it < 4; it++) {
        int idx = tid + it*256;
        int r = idx >> 4, d0 = (idx & 15) * 4;
        *(uint2*)(Qs + r*T_LD + d0) = *(const uint2*)(qsrc + r*HD + d0);
    }
    {
        int4 m4 = *(const int4*)(pmask + (size_t)mb*SEQ + tid*4);
        float4 f4;
        f4.x = m4.x ? 1.f : 0.f; f4.y = m4.y ? 1.f : 0.f;
        f4.z = m4.z ? 1.f : 0.f; f4.w = m4.w ? 1.f : 0.f;
        *(float4*)(mm + tid*4) = f4;
    }

    const __half* ksrc = g_K + (size_t)n*SEQ*HD;
    const __half* vsrc = g_V + (size_t)n*SEQ*HD;
    const int lr = tid >> 4, ld0 = (tid & 15) * 4;

    float o[8][4];          // 16 rows x 64 out cols, partial over warp's keys
    #pragma unroll
    for (int j = 0; j < 8; j++)
        #pragma unroll
        for (int e = 0; e < 4; e++) o[j][e] = 0.f;
    float rs[2] = {0.f, 0.f};

    uint2 rk[4], rv[4];
    #pragma unroll
    for (int it = 0; it < 4; it++) {
        int t = lr + it*16;
        rk[it] = *(const uint2*)(ksrc + (size_t)t*HD + ld0);
        rv[it] = *(const uint2*)(vsrc + (size_t)t*HD + ld0);
    }

    const unsigned qb = su(Qs), kb = su(Ks), vb = su(Vs);
    const size_t rowg = (size_t)n*SEQ + (size_t)qt*QT_ROWS;

    for (int kt = 0; kt < 16; ++kt) {
        __syncthreads();   // prior iter's K/V reads complete
        #pragma unroll
        for (int it = 0; it < 4; it++) {
            int t = lr + it*16;
            *(uint2*)(Ks + t*T_LD + ld0) = rk[it];
            *(uint2*)(Vs + t*T_LD + ld0) = rv[it];
        }
        __syncthreads();

        // ---- S = (Q/8) K^T : 16 rows x 32 keys ----
        float s[4][4];
        #pragma unroll
        for (int j = 0; j < 4; j++)
            #pragma unroll
            for (int e = 0; e < 4; e++) s[j][e] = 0.f;

        #pragma unroll
        for (int kf = 0; kf < 4; kf++) {
            unsigned a[4], b[4][2];
            ldsm4(a[0], a[1], a[2], a[3],
                  qb + ((wm*16 + a_r)*T_LD + kf*16 + a_c)*2);
            #pragma unroll
            for (int nb = 0; nb < 2; nb++) {
                unsigned r0, r1, r2, r3;
                ldsm4(r0, r1, r2, r3,
                      kb + ((wn*32 + nb*16 + b_r)*T_LD + kf*16 + b_c)*2);
                b[nb*2+0][0] = r0; b[nb*2+0][1] = r1;
                b[nb*2+1][0] = r2; b[nb*2+1][1] = r3;
            }
            #pragma unroll
            for (int nf = 0; nf < 4; nf++)
                mma_f16(s[nf], a, b[nf]);
        }

        // ---- raw write + mask + exp, packed into PV A-fragments ----
        unsigned ph[4][2];
        {
            int r0 = wm*16 + quad;
            #pragma unroll
            for (int nf = 0; nf < 4; nf++) {
                int lcol = wn*32 + nf*8 + lane4*2;
                int col  = kt*64 + lcol;
                __stcs((float2*)(raw + (rowg + r0)*SEQ + col),
                       make_float2(s[nf][0], s[nf][1]));
                __stcs((float2*)(raw + (rowg + r0 + 8)*SEQ + col),
                       make_float2(s[nf][2], s[nf][3]));
                float2 m2 = *(const float2*)(mm + col);
                float p00 = m2.x * __expf(s[nf][0]);
                float p01 = m2.y * __expf(s[nf][1]);
                float p10 = m2.x * __expf(s[nf][2]);
                float p11 = m2.y * __expf(s[nf][3]);
                rs[0] += p00 + p01;
                rs[1] += p10 + p11;
                ph[nf][0] = h2u(p00, p01);
                ph[nf][1] = h2u(p10, p11);
            }
        }

        if (kt < 15) {     // prefetch next K/V; overlaps PV mma
            #pragma unroll
            for (int it = 0; it < 4; it++) {
                int t = (kt+1)*64 + lr + it*16;
                rk[it] = *(const uint2*)(ksrc + (size_t)t*HD + ld0);
                rv[it] = *(const uint2*)(vsrc + (size_t)t*HD + ld0);
            }
        }

        // ---- O += P @ V over warp's own 32 keys, all 64 out cols ----
        #pragma unroll
        for (int tf = 0; tf < 2; tf++) {
            unsigned a[4], b[8][2];
            a[0] = ph[2*tf+0][0];
            a[1] = ph[2*tf+0][1];
            a[2] = ph[2*tf+1][0];
            a[3] = ph[2*tf+1][1];
            #pragma unroll
            for (int nb = 0; nb < 4; nb++) {
                unsigned r0, r1, r2, r3;
                ldsm4t(r0, r1, r2, r3,
                       vb + ((wn*32 + tf*16 + (sub & 1)*8 + lr8)*T_LD
                             + nb*16 + (sub >> 1)*8)*2);
                b[nb*2+0][0] = r0; b[nb*2+0][1] = r1;
                b[nb*2+1][0] = r2; b[nb*2+1][1] = r3;
            }
            #pragma unroll
            for (int nf = 0; nf < 8; nf++)
                mma_f16(o[nf], a, b[nf]);
        }
    }

    // ---- row-sum reduce across lane4; publish per key-half ----
    rs[0] += __shfl_xor_sync(0xffffffffu, rs[0], 1);
    rs[0] += __shfl_xor_sync(0xffffffffu, rs[0], 2);
    rs[1] += __shfl_xor_sync(0xffffffffu, rs[1], 1);
    rs[1] += __shfl_xor_sync(0xffffffffu, rs[1], 2);

    __syncthreads();   // all smem-tile reads done; safe to alias ob
    {
        int r0 = wm*16 + quad;
        if (lane4 == 0) {
            ls[wn*64 + r0]     = rs[0];
            ls[wn*64 + r0 + 8] = rs[1];
        }
        if (wn == 1) {
            #pragma unroll
            for (int nf = 0; nf < 8; nf++) {
                int col = nf*8 + lane4*2;
                *(float2*)(ob + r0*64 + col)     = make_float2(o[nf][0], o[nf][1]);
                *(float2*)(ob + (r0+8)*64 + col) = make_float2(o[nf][2], o[nf][3]);
            }
        }
    }
    __syncthreads();

    if (wn == 0) {     // combine halves, normalize, store fp16
        int r0 = wm*16 + quad;
        float inv0 = 1.f / (ls[r0] + ls[64 + r0]);
        float inv1 = 1.f / (ls[r0 + 8] + ls[64 + r0 + 8]);
        __half* adst = g_A + (rowg + r0)*HD;
        #pragma unroll
        for (int nf = 0; nf < 8; nf++) {
            int col = nf*8 + lane4*2;
            float2 p0 = *(const float2*)(ob + r0*64 + col);
            float2 p1 = *(const float2*)(ob + (r0+8)*64 + col);
            *(__half2*)(adst + col) =
                __floats2half2_rn((o[nf][0] + p0.x)*inv0,
                                  (o[nf][1] + p0.y)*inv0);
            *(__half2*)(adst + 8*HD + col) =
                __floats2half2_rn((o[nf][2] + p1.x)*inv1,
                                  (o[nf][3] + p1.y)*inv1);
        }
    }
}

// ---------------------------------------------------------------------------
// Output projection (unchanged from R11).
// ---------------------------------------------------------------------------
__global__ __launch_bounds__(256, 2) void proj_out_kernel(
    const float* __restrict__ bo, float* __restrict__ out)
{
    __shared__ __half As[2][128*A_LD];
    __shared__ __half Bs[2][32*B_LD];

    const __half* w = g_wh[3];
    const int m0 = blockIdx.x * 128;
    const int n0 = blockIdx.y * 128;
    const int tid = threadIdx.x;
    const int wid = tid >> 5, lane = tid & 31;
    const int wm = wid >> 1, wn = wid & 1;
    const int quad = lane >> 2, lane4 = lane & 3;
    const int sub = lane >> 3, lr8 = lane & 7;
    const int a_r = (sub & 1)*8 + lr8, a_c = (sub >> 1)*8;

    const int ar = tid >> 3, ac = (tid & 7) * 4;
    const int br = tid >> 5, bc = (tid & 31) * 4;
    const int rowA0 = m0 + ar;

    float o[2][8][4];
    #pragma unroll
    for (int i = 0; i < 2; i++)
        #pragma unroll
        for (int j = 0; j < 8; j++)
            #pragma unroll
            for (int e = 0; e < 4; e++) o[i][j][e] = 0.f;

    float2 bias2[8];
    #pragma unroll
    for (int nf = 0; nf < 8; nf++)
        bias2[nf] = *(const float2*)(bo + n0 + wn*64 + nf*8 + lane4*2);

    uint2 ra[4], rb[4];
    #pragma unroll
    for (int it = 0; it < 4; it++) {
        int row = rowA0 + it*32;
        int b = row >> 10, s = row & 1023;
        ra[it] = *(const uint2*)(g_A + ((size_t)b*SEQ + s)*HD + ac);
    }
    #pragma unroll
    for (int it = 0; it < 4; it++)
        rb[it] = *(const uint2*)(w + (size_t)(br + it*8)*DM + n0 + bc);

    const unsigned ab[2] = {su(As[0]), su(As[1])};
    const unsigned bb[2] = {su(Bs[0]), su(Bs[1])};

    for (int kt = 0; kt < 16; kt++) {
        const int cb = kt & 1;
        #pragma unroll
        for (int it = 0; it < 4; it++)
            *(uint2*)(As[cb] + (ar + it*32)*A_LD + ac) = ra[it];
        #pragma unroll
        for (int it = 0; it < 4; it++)
            *(uint2*)(Bs[cb] + (br + it*8)*B_LD + bc) = rb[it];
        __syncthreads();

        if (kt < 15) {
            int k0 = (kt + 1) * 32;
            int h = k0 >> 6, v0 = k0 & 63;
            #pragma unroll
            for (int it = 0; it < 4; it++) {
                int row = rowA0 + it*32;
                int b = row >> 10, s = row & 1023;
                ra[it] = *(const uint2*)(g_A + (((size_t)(h*BATCH + b))*SEQ + s)*HD + v0 + ac);
            }
            #pragma unroll
            for (int it = 0; it < 4; it++)
                rb[it] = *(const uint2*)(w + (size_t)(k0 + br + it*8)*DM + n0 + bc);
        }

        #pragma unroll
        for (int kf = 0; kf < 2; kf++) {
            unsigned a[2][4], b[8][2];
            #pragma unroll
            for (int mf = 0; mf < 2; mf++)
                ldsm4(a[mf][0], a[mf][1], a[mf][2], a[mf][3],
                      ab[cb] + ((wm*32 + mf*16 + a_r)*A_LD + kf*16 + a_c)*2);
            #pragma unroll
            for (int nb = 0; nb < 4; nb++) {
                unsigned r0, r1, r2, r3;
                ldsm4t(r0, r1, r2, r3,
                       bb[cb] + ((kf*16 + (sub & 1)*8 + lr8)*B_LD
                                 + wn*64 + nb*16 + (sub >> 1)*8)*2);
                b[nb*2+0][0] = r0; b[nb*2+0][1] = r1;
                b[nb*2+1][0] = r2; b[nb*2+1][1] = r3;
            }
            #pragma unroll
            for (int mf = 0; mf < 2; mf++)
                #pragma unroll
                for (int nf = 0; nf < 8; nf++)
                    mma_f16(o[mf][nf], a[mf], b[nf]);
        }
    }

    #pragma unroll
    for (int mf = 0; mf < 2; mf++) {
        int row0 = m0 + wm*32 + mf*16 + quad;
        #pragma unroll
        for (int nf = 0; nf < 8; nf++) {
            int col = n0 + wn*64 + nf*8 + lane4*2;
            __stcs((float2*)(out + (size_t)row0*DM + col),
                   make_float2(o[mf][nf][0] + bias2[nf].x,
                               o[mf][nf][1] + bias2[nf].y));
            __stcs((float2*)(out + (size_t)(row0+8)*DM + col),
                   make_float2(o[mf][nf][2] + bias2[nf].x,
                               o[mf][nf][3] + bias2[nf].y));
        }
    }
}

// ---------------------------------------------------------------------------
extern "C" void kernel_launch(void* const* d_in, const int* in_sizes, int n_in,
                              void* d_out, int out_size)
{
    (void)in_sizes; (void)n_in; (void)out_size;
    const float* x  = (const float*)d_in[0];
    const int*   pm = (const int*)  d_in[1];
    const float* wq = (const float*)d_in[2];
    const float* bq = (const float*)d_in[3];
    const float* wk = (const float*)d_in[4];
    const float* bk = (const float*)d_in[5];
    const float* wv = (const float*)d_in[6];
    const float* bv = (const float*)d_in[7];
    const float* wo = (const float*)d_in[8];
    const float* bo = (const float*)d_in[9];

    float* out = (float*)d_out;
    float* raw = out + (size_t)BATCH*SEQ*DM;

    cudaFuncSetAttribute(attn_kernel, cudaFuncAttributeMaxDynamicSharedMemorySize,
                         ATTN_SMEM);

    __half* xh;
    cudaGetSymbolAddress((void**)&xh, g_xh);

    const int NX = BATCH*SEQ*DM, NW = DM*DM;
    cvt_kernel<<<NX/1024, 256>>>(x, xh, NX);
    cvt_w_kernel<<<dim3(NW/1024, 4), 256>>>(wq, wk, wv, wo);

    proj_qkv_kernel<<<dim3(BATCH*SEQ/128, DM/128, 3), 256>>>(bq, bk, bv);
    attn_kernel<<<dim3(SEQ/QT_ROWS, NB), 256, ATTN_SMEM>>>(pm, raw);
    proj_out_kernel<<<dim3(BATCH*SEQ/128, DM/128), 256>>>(bo, out);
}

// round 15
// speedup vs baseline: 1.2016x; 1.1172x over previous
#include <cuda_runtime.h>
#include <cuda_fp16.h>
#include <math.h>

#define BATCH 16
#define SEQ   1024
#define DM    512
#define NH    8
#define HD    64
#define NB    (NH*BATCH)

#define A_LD  40    // proj A tile pitch (halves)
#define B_LD  136   // proj B tile pitch (halves), 128+8
#define T_LD  72    // attn Q/K/V/P tile pitch (halves)
#define KBUF  (64*T_LD)    // K/V buffer stride (halves)
#define PBUF  (128*T_LD)   // P buffer stride (halves)

// Scratch, fp16 (device globals: allocation-free per harness rules).
__device__ __half g_Q[(size_t)NB*SEQ*HD];   // pre-scaled by 0.125
__device__ __half g_K[(size_t)NB*SEQ*HD];
__device__ __half g_V[(size_t)NB*SEQ*HD];
__device__ __half g_A[(size_t)NB*SEQ*HD];
__device__ __half g_xh[(size_t)BATCH*SEQ*DM];   // fp16 copy of x
__device__ __half g_wh[4][(size_t)DM*DM];       // fp16 wq,wk,wv,wo

__device__ __forceinline__ void st_h4(__half* p, float4 v) {
    __half2 lo = __floats2half2_rn(v.x, v.y);
    __half2 hi = __floats2half2_rn(v.z, v.w);
    uint2 u;
    u.x = *(unsigned int*)&lo;
    u.y = *(unsigned int*)&hi;
    *(uint2*)p = u;
}

// ---------------------------------------------------------------------------
// PTX mma/ldmatrix helpers
// ---------------------------------------------------------------------------
__device__ __forceinline__ unsigned su(const void* p) {
    return (unsigned)__cvta_generic_to_shared(p);
}
__device__ __forceinline__ void ldsm4(unsigned& r0, unsigned& r1,
                                      unsigned& r2, unsigned& r3, unsigned a) {
    asm volatile("ldmatrix.sync.aligned.m8n8.x4.shared.b16 {%0,%1,%2,%3},[%4];"
                 : "=r"(r0), "=r"(r1), "=r"(r2), "=r"(r3) : "r"(a));
}
__device__ __forceinline__ void ldsm4t(unsigned& r0, unsigned& r1,
                                       unsigned& r2, unsigned& r3, unsigned a) {
    asm volatile("ldmatrix.sync.aligned.m8n8.x4.trans.shared.b16 {%0,%1,%2,%3},[%4];"
                 : "=r"(r0), "=r"(r1), "=r"(r2), "=r"(r3) : "r"(a));
}
__device__ __forceinline__ void mma_f16(float* d, const unsigned* a,
                                        const unsigned* b) {
    asm volatile("mma.sync.aligned.m16n8k16.row.col.f32.f16.f16.f32 "
                 "{%0,%1,%2,%3},{%4,%5,%6,%7},{%8,%9},{%0,%1,%2,%3};"
                 : "+f"(d[0]), "+f"(d[1]), "+f"(d[2]), "+f"(d[3])
                 : "r"(a[0]), "r"(a[1]), "r"(a[2]), "r"(a[3]),
                   "r"(b[0]), "r"(b[1]));
}

// ---------------------------------------------------------------------------
// fp32 -> fp16 conversion prep kernels
// ---------------------------------------------------------------------------
__global__ __launch_bounds__(256) void cvt_kernel(const float* __restrict__ src,
                                                  __half* __restrict__ dst, int n) {
    int i = (blockIdx.x * 256 + threadIdx.x) * 4;
    if (i < n) st_h4(dst + i, *(const float4*)(src + i));
}
__global__ __launch_bounds__(256) void cvt_w_kernel(
    const float* __restrict__ wq, const float* __restrict__ wk,
    const float* __restrict__ wv, const float* __restrict__ wo) {
    const float* src = (blockIdx.y == 0) ? wq : (blockIdx.y == 1) ? wk
                     : (blockIdx.y == 2) ? wv : wo;
    __half* dst = g_wh[blockIdx.y];
    int i = (blockIdx.x * 256 + threadIdx.x) * 4;
    st_h4(dst + i, *(const float4*)(src + i));
}

// ---------------------------------------------------------------------------
// QKV projection (R10 form: single-buffered smem, PTX mma, register epilogue).
// ---------------------------------------------------------------------------
__global__ __launch_bounds__(256, 2) void proj_qkv_kernel(
    const float* __restrict__ bq, const float* __restrict__ bk,
    const float* __restrict__ bv)
{
    __shared__ __half As[128*A_LD];
    __shared__ __half Bs[32*B_LD];

    const float* bias; __half* dst; float oscale;
    const __half* w = g_wh[blockIdx.z];
    if (blockIdx.z == 0)      { bias = bq; dst = g_Q; oscale = 0.125f; }
    else if (blockIdx.z == 1) { bias = bk; dst = g_K; oscale = 1.f; }
    else                      { bias = bv; dst = g_V; oscale = 1.f; }

    const int m0 = blockIdx.x * 128;
    const int n0 = blockIdx.y * 128;
    const int tid = threadIdx.x;
    const int wid = tid >> 5, lane = tid & 31;
    const int wm = wid >> 1, wn = wid & 1;
    const int quad = lane >> 2, lane4 = lane & 3;
    const int sub = lane >> 3, lr8 = lane & 7;
    const int a_r = (sub & 1)*8 + lr8, a_c = (sub >> 1)*8;

    const int ar = tid >> 3, ac = (tid & 7) * 4;
    const int br = tid >> 5, bc = (tid & 31) * 4;

    float o[2][8][4];
    #pragma unroll
    for (int i = 0; i < 2; i++)
        #pragma unroll
        for (int j = 0; j < 8; j++)
            #pragma unroll
            for (int e = 0; e < 4; e++) o[i][j][e] = 0.f;

    float2 bias2[8];
    #pragma unroll
    for (int nf = 0; nf < 8; nf++)
        bias2[nf] = *(const float2*)(bias + n0 + wn*64 + nf*8 + lane4*2);

    uint2 ra[4], rb[4];
    #pragma unroll
    for (int it = 0; it < 4; it++)
        ra[it] = *(const uint2*)(g_xh + (size_t)(m0 + ar + it*32)*DM + ac);
    #pragma unroll
    for (int it = 0; it < 4; it++)
        rb[it] = *(const uint2*)(w + (size_t)(br + it*8)*DM + n0 + bc);

    const unsigned ab = su(As), bb = su(Bs);

    for (int kt = 0; kt < 16; kt++) {
        __syncthreads();
        #pragma unroll
        for (int it = 0; it < 4; it++)
            *(uint2*)(As + (ar + it*32)*A_LD + ac) = ra[it];
        #pragma unroll
        for (int it = 0; it < 4; it++)
            *(uint2*)(Bs + (br + it*8)*B_LD + bc) = rb[it];
        __syncthreads();

        if (kt < 15) {
            int k0 = (kt + 1) * 32;
            #pragma unroll
            for (int it = 0; it < 4; it++)
                ra[it] = *(const uint2*)(g_xh + (size_t)(m0 + ar + it*32)*DM + k0 + ac);
            #pragma unroll
            for (int it = 0; it < 4; it++)
                rb[it] = *(const uint2*)(w + (size_t)(k0 + br + it*8)*DM + n0 + bc);
        }

        #pragma unroll
        for (int kf = 0; kf < 2; kf++) {
            unsigned a[2][4], b[8][2];
            #pragma unroll
            for (int mf = 0; mf < 2; mf++)
                ldsm4(a[mf][0], a[mf][1], a[mf][2], a[mf][3],
                      ab + ((wm*32 + mf*16 + a_r)*A_LD + kf*16 + a_c)*2);
            #pragma unroll
            for (int nb = 0; nb < 4; nb++) {
                unsigned r0, r1, r2, r3;
                ldsm4t(r0, r1, r2, r3,
                       bb + ((kf*16 + (sub & 1)*8 + lr8)*B_LD
                             + wn*64 + nb*16 + (sub >> 1)*8)*2);
                b[nb*2+0][0] = r0; b[nb*2+0][1] = r1;
                b[nb*2+1][0] = r2; b[nb*2+1][1] = r3;
            }
            #pragma unroll
            for (int mf = 0; mf < 2; mf++)
                #pragma unroll
                for (int nf = 0; nf < 8; nf++)
                    mma_f16(o[mf][nf], a[mf], b[nf]);
        }
    }

    #pragma unroll
    for (int mf = 0; mf < 2; mf++) {
        int row0 = m0 + wm*32 + mf*16 + quad;
        int b0 = row0 >> 10, s0 = row0 & 1023;
        int row1 = row0 + 8;
        int b1 = row1 >> 10, s1 = row1 & 1023;
        #pragma unroll
        for (int nf = 0; nf < 8; nf++) {
            int col = n0 + wn*64 + nf*8 + lane4*2;
            int h = col >> 6, q0 = col & 63;
            *(__half2*)(dst + (((size_t)(h*BATCH + b0))*SEQ + s0)*HD + q0) =
                __floats2half2_rn((o[mf][nf][0] + bias2[nf].x) * oscale,
                                  (o[mf][nf][1] + bias2[nf].y) * oscale);
            *(__half2*)(dst + (((size_t)(h*BATCH + b1))*SEQ + s1)*HD + q0) =
                __floats2half2_rn((o[mf][nf][2] + bias2[nf].x) * oscale,
                                  (o[mf][nf][3] + bias2[nf].y) * oscale);
        }
    }
}

// ---------------------------------------------------------------------------
// Fused attention: R11 col-split compute with single-barrier pipeline.
// K/V triple-buffered, P double-buffered => 1 __syncthreads per k-tile.
// Warp (wm, wn): S = 32 rows x keys wn*32..+32; PV = 32 rows x out cols
// wn*32..+32 over ALL 64 keys (o[2][4][4], two ldsm4t per 16-key chunk).
// ---------------------------------------------------------------------------
#define QT_ROWS 128
#define ATTN_SMEM ((128*T_LD + 2*PBUF + 6*KBUF)*2 + 2*128*4)

__global__ __launch_bounds__(256, 2) void attn_kernel(const int* __restrict__ pmask,
                                                      float* __restrict__ raw)
{
    extern __shared__ char shb[];
    __half* Qs  = (__half*)shb;                // [128][72]
    __half* Ps  = Qs + 128*T_LD;               // 2 x [128][72]
    __half* Ksb = Ps + 2*PBUF;                 // 3 x [64][72]
    __half* Vsb = Ksb + 3*KBUF;                // 3 x [64][72]
    float*  ls  = (float*)(Vsb + 3*KBUF);      // [2][128]

    const int n  = blockIdx.y;
    const int qt = blockIdx.x;
    const int tid = threadIdx.x;
    const int wid = tid >> 5, lane = tid & 31;
    const int wm = wid >> 1, wn = wid & 1;
    const int quad = lane >> 2, lane4 = lane & 3;
    const int sub = lane >> 3, lr8 = lane & 7;
    const int mb = n >> 3;                     // faithful mask-index mismatch

    const int a_r = (sub & 1)*8 + lr8, a_c = (sub >> 1)*8;
    const int b_r = (sub >> 1)*8 + lr8, b_c = (sub & 1)*8;

    const __half* qsrc = g_Q + ((size_t)n*SEQ + qt*128)*HD;
    #pragma unroll
    for (int it = 0; it < 8; it++) {
        int idx = tid + it*256;
        int r = idx >> 4, d0 = (idx & 15) * 4;
        *(uint2*)(Qs + r*T_LD + d0) = *(const uint2*)(qsrc + r*HD + d0);
    }

    const __half* ksrc = g_K + (size_t)n*SEQ*HD;
    const __half* vsrc = g_V + (size_t)n*SEQ*HD;
    const int*    msrc = pmask + (size_t)mb*SEQ;
    const int lr = tid >> 4, ld0 = (tid & 15) * 4;

    float o[2][4][4];
    #pragma unroll
    for (int i = 0; i < 2; i++)
        #pragma unroll
        for (int j = 0; j < 4; j++)
            #pragma unroll
            for (int e = 0; e < 4; e++) o[i][j][e] = 0.f;
    float rs[2][2] = {{0.f, 0.f}, {0.f, 0.f}};

    // Prologue: tile 0 -> buf 0; tile 1 -> regs; sync publishes Q/K0/V0.
    uint2 rk[4], rv[4];
    #pragma unroll
    for (int it = 0; it < 4; it++) {
        int t = lr + it*16;
        rk[it] = *(const uint2*)(ksrc + (size_t)t*HD + ld0);
        rv[it] = *(const uint2*)(vsrc + (size_t)t*HD + ld0);
    }
    #pragma unroll
    for (int it = 0; it < 4; it++) {
        int t = lr + it*16;
        *(uint2*)(Ksb + t*T_LD + ld0) = rk[it];
        *(uint2*)(Vsb + t*T_LD + ld0) = rv[it];
    }
    #pragma unroll
    for (int it = 0; it < 4; it++) {
        int t = 64 + lr + it*16;
        rk[it] = *(const uint2*)(ksrc + (size_t)t*HD + ld0);
        rv[it] = *(const uint2*)(vsrc + (size_t)t*HD + ld0);
    }
    __syncthreads();

    const unsigned qb = su(Qs), pb0 = su(Ps), kb0 = su(Ksb), vb0 = su(Vsb);
    const size_t rowg = (size_t)n*SEQ + (size_t)qt*128;

    for (int kt = 0; kt < 16; ++kt) {
        const int cb = kt % 3;
        const int pc = kt & 1;
        const unsigned kb = kb0 + cb*KBUF*2;
        const unsigned vb = vb0 + cb*KBUF*2;
        const unsigned pbw = pb0 + pc*PBUF*2;
        __half* Pw = Ps + pc*PBUF;

        // ---- S = (Q/8) K^T : warp 32 rows x 32 keys ----
        float s[2][4][4];
        #pragma unroll
        for (int i = 0; i < 2; i++)
            #pragma unroll
            for (int j = 0; j < 4; j++)
                #pragma unroll
                for (int e = 0; e < 4; e++) s[i][j][e] = 0.f;

        #pragma unroll
        for (int kf = 0; kf < 4; kf++) {
            unsigned a[2][4], b[4][2];
            #pragma unroll
            for (int mf = 0; mf < 2; mf++)
                ldsm4(a[mf][0], a[mf][1], a[mf][2], a[mf][3],
                      qb + ((wm*32 + mf*16 + a_r)*T_LD + kf*16 + a_c)*2);
            #pragma unroll
            for (int nb = 0; nb < 2; nb++) {
                unsigned r0, r1, r2, r3;
                ldsm4(r0, r1, r2, r3,
                      kb + ((wn*32 + nb*16 + b_r)*T_LD + kf*16 + b_c)*2);
                b[nb*2+0][0] = r0; b[nb*2+0][1] = r1;
                b[nb*2+1][0] = r2; b[nb*2+1][1] = r3;
            }
            #pragma unroll
            for (int mf = 0; mf < 2; mf++)
                #pragma unroll
                for (int nf = 0; nf < 4; nf++)
                    mma_f16(s[mf][nf], a[mf], b[nf]);
        }

        // ---- raw write (stcs) + mask (cached global) + exp -> P[pc] ----
        #pragma unroll
        for (int mf = 0; mf < 2; mf++) {
            int r0 = wm*32 + mf*16 + quad;
            #pragma unroll
            for (int nf = 0; nf < 4; nf++) {
                int lcol = wn*32 + nf*8 + lane4*2;
                int col  = kt*64 + lcol;
                __stcs((float2*)(raw + (rowg + r0)*SEQ + col),
                       make_float2(s[mf][nf][0], s[mf][nf][1]));
                __stcs((float2*)(raw + (rowg + r0 + 8)*SEQ + col),
                       make_float2(s[mf][nf][2], s[mf][nf][3]));
                int2 mk = *(const int2*)(msrc + col);
                float mx = mk.x ? 1.f : 0.f;
                float my = mk.y ? 1.f : 0.f;
                float p00 = mx * __expf(s[mf][nf][0]);
                float p01 = my * __expf(s[mf][nf][1]);
                float p10 = mx * __expf(s[mf][nf][2]);
                float p11 = my * __expf(s[mf][nf][3]);
                rs[mf][0] += p00 + p01;
                rs[mf][1] += p10 + p11;
                *(__half2*)(Pw + r0*T_LD + lcol)     = __floats2half2_rn(p00, p01);
                *(__half2*)(Pw + (r0+8)*T_LD + lcol) = __floats2half2_rn(p10, p11);
            }
        }

        // ---- stage tile kt+1 into buffer (kt+1)%3; prefetch kt+2 ----
        if (kt < 15) {
            const int nbuf = (kt + 1) % 3;
            #pragma unroll
            for (int it = 0; it < 4; it++) {
                int t = lr + it*16;
                *(uint2*)(Ksb + nbuf*KBUF + t*T_LD + ld0) = rk[it];
                *(uint2*)(Vsb + nbuf*KBUF + t*T_LD + ld0) = rv[it];
            }
        }
        if (kt < 14) {
            #pragma unroll
            for (int it = 0; it < 4; it++) {
                int t = (kt+2)*64 + lr + it*16;
                rk[it] = *(const uint2*)(ksrc + (size_t)t*HD + ld0);
                rv[it] = *(const uint2*)(vsrc + (size_t)t*HD + ld0);
            }
        }

        __syncthreads();   // P[pc] + K/V[(kt+1)%3] published

        // ---- O += P @ V : warp 32 rows x out cols wn*32..+32, all 64 keys ----
        #pragma unroll
        for (int tf = 0; tf < 4; tf++) {
            unsigned b[4][2];
            #pragma unroll
            for (int nb = 0; nb < 2; nb++) {
                unsigned r0, r1, r2, r3;
                ldsm4t(r0, r1, r2, r3,
                       vb + ((tf*16 + (sub & 1)*8 + lr8)*T_LD
                             + wn*32 + nb*16 + (sub >> 1)*8)*2);
                b[nb*2+0][0] = r0; b[nb*2+0][1] = r1;
                b[nb*2+1][0] = r2; b[nb*2+1][1] = r3;
            }
            #pragma unroll
            for (int mf = 0; mf < 2; mf++) {
                unsigned pa[4];
                ldsm4(pa[0], pa[1], pa[2], pa[3],
                      pbw + ((wm*32 + mf*16 + a_r)*T_LD + tf*16 + a_c)*2);
                #pragma unroll
                for (int nf = 0; nf < 4; nf++)
                    mma_f16(o[mf][nf], pa, b[nf]);
            }
        }
    }

    // ---- epilogue: row sums, normalize, store fp16 ----
    #pragma unroll
    for (int mf = 0; mf < 2; mf++)
        #pragma unroll
        for (int rg = 0; rg < 2; rg++) {
            rs[mf][rg] += __shfl_xor_sync(0xffffffffu, rs[mf][rg], 1);
            rs[mf][rg] += __shfl_xor_sync(0xffffffffu, rs[mf][rg], 2);
        }
    if (lane4 == 0) {
        #pragma unroll
        for (int mf = 0; mf < 2; mf++) {
            int r0 = wm*32 + mf*16 + quad;
            ls[wn*128 + r0]     = rs[mf][0];
            ls[wn*128 + r0 + 8] = rs[mf][1];
        }
    }
    __syncthreads();

    #pragma unroll
    for (int mf = 0; mf < 2; mf++) {
        int r0 = wm*32 + mf*16 + quad;
        float inv0 = 1.f / (ls[r0] + ls[128 + r0]);
        float inv1 = 1.f / (ls[r0 + 8] + ls[128 + r0 + 8]);
        __half* adst = g_A + (rowg + r0)*HD;
        #pragma unroll
        for (int nf = 0; nf < 4; nf++) {
            int col = wn*32 + nf*8 + lane4*2;
            *(__half2*)(adst + col) =
                __floats2half2_rn(o[mf][nf][0]*inv0, o[mf][nf][1]*inv0);
            *(__half2*)(adst + 8*HD + col) =
                __floats2half2_rn(o[mf][nf][2]*inv1, o[mf][nf][3]*inv1);
        }
    }
}

// ---------------------------------------------------------------------------
// Output projection (R10 form).
// ---------------------------------------------------------------------------
__global__ __launch_bounds__(256, 2) void proj_out_kernel(
    const float* __restrict__ bo, float* __restrict__ out)
{
    __shared__ __half As[128*A_LD];
    __shared__ __half Bs[32*B_LD];

    const __half* w = g_wh[3];
    const int m0 = blockIdx.x * 128;
    const int n0 = blockIdx.y * 128;
    const int tid = threadIdx.x;
    const int wid = tid >> 5, lane = tid & 31;
    const int wm = wid >> 1, wn = wid & 1;
    const int quad = lane >> 2, lane4 = lane & 3;
    const int sub = lane >> 3, lr8 = lane & 7;
    const int a_r = (sub & 1)*8 + lr8, a_c = (sub >> 1)*8;

    const int ar = tid >> 3, ac = (tid & 7) * 4;
    const int br = tid >> 5, bc = (tid & 31) * 4;
    const int rowA0 = m0 + ar;

    float o[2][8][4];
    #pragma unroll
    for (int i = 0; i < 2; i++)
        #pragma unroll
        for (int j = 0; j < 8; j++)
            #pragma unroll
            for (int e = 0; e < 4; e++) o[i][j][e] = 0.f;

    float2 bias2[8];
    #pragma unroll
    for (int nf = 0; nf < 8; nf++)
        bias2[nf] = *(const float2*)(bo + n0 + wn*64 + nf*8 + lane4*2);

    uint2 ra[4], rb[4];
    #pragma unroll
    for (int it = 0; it < 4; it++) {
        int row = rowA0 + it*32;
        int b = row >> 10, s = row & 1023;
        ra[it] = *(const uint2*)(g_A + ((size_t)b*SEQ + s)*HD + ac);
    }
    #pragma unroll
    for (int it = 0; it < 4; it++)
        rb[it] = *(const uint2*)(w + (size_t)(br + it*8)*DM + n0 + bc);

    const unsigned ab = su(As), bb = su(Bs);

    for (int kt = 0; kt < 16; kt++) {
        __syncthreads();
        #pragma unroll
        for (int it = 0; it < 4; it++)
            *(uint2*)(As + (ar + it*32)*A_LD + ac) = ra[it];
        #pragma unroll
        for (int it = 0; it < 4; it++)
            *(uint2*)(Bs + (br + it*8)*B_LD + bc) = rb[it];
        __syncthreads();

        if (kt < 15) {
            int k0 = (kt + 1) * 32;
            int h = k0 >> 6, v0 = k0 & 63;
            #pragma unroll
            for (int it = 0; it < 4; it++) {
                int row = rowA0 + it*32;
                int b = row >> 10, s = row & 1023;
                ra[it] = *(const uint2*)(g_A + (((size_t)(h*BATCH + b))*SEQ + s)*HD + v0 + ac);
            }
            #pragma unroll
            for (int it = 0; it < 4; it++)
                rb[it] = *(const uint2*)(w + (size_t)(k0 + br + it*8)*DM + n0 + bc);
        }

        #pragma unroll
        for (int kf = 0; kf < 2; kf++) {
            unsigned a[2][4], b[8][2];
            #pragma unroll
            for (int mf = 0; mf < 2; mf++)
                ldsm4(a[mf][0], a[mf][1], a[mf][2], a[mf][3],
                      ab + ((wm*32 + mf*16 + a_r)*A_LD + kf*16 + a_c)*2);
            #pragma unroll
            for (int nb = 0; nb < 4; nb++) {
                unsigned r0, r1, r2, r3;
                ldsm4t(r0, r1, r2, r3,
                       bb + ((kf*16 + (sub & 1)*8 + lr8)*B_LD
                             + wn*64 + nb*16 + (sub >> 1)*8)*2);
                b[nb*2+0][0] = r0; b[nb*2+0][1] = r1;
                b[nb*2+1][0] = r2; b[nb*2+1][1] = r3;
            }
            #pragma unroll
            for (int mf = 0; mf < 2; mf++)
                #pragma unroll
                for (int nf = 0; nf < 8; nf++)
                    mma_f16(o[mf][nf], a[mf], b[nf]);
        }
    }

    #pragma unroll
    for (int mf = 0; mf < 2; mf++) {
        int row0 = m0 + wm*32 + mf*16 + quad;
        #pragma unroll
        for (int nf = 0; nf < 8; nf++) {
            int col = n0 + wn*64 + nf*8 + lane4*2;
            __stcs((float2*)(out + (size_t)row0*DM + col),
                   make_float2(o[mf][nf][0] + bias2[nf].x,
                               o[mf][nf][1] + bias2[nf].y));
            __stcs((float2*)(out + (size_t)(row0+8)*DM + col),
                   make_float2(o[mf][nf][2] + bias2[nf].x,
                               o[mf][nf][3] + bias2[nf].y));
        }
    }
}

// ---------------------------------------------------------------------------
extern "C" void kernel_launch(void* const* d_in, const int* in_sizes, int n_in,
                              void* d_out, int out_size)
{
    (void)in_sizes; (void)n_in; (void)out_size;
    const float* x  = (const float*)d_in[0];
    const int*   pm = (const int*)  d_in[1];
    const float* wq = (const float*)d_in[2];
    const float* bq = (const float*)d_in[3];
    const float* wk = (const float*)d_in[4];
    const float* bk = (const float*)d_in[5];
    const float* wv = (const float*)d_in[6];
    const float* bv = (const float*)d_in[7];
    const float* wo = (const float*)d_in[8];
    const float* bo = (const float*)d_in[9];

    float* out = (float*)d_out;
    float* raw = out + (size_t)BATCH*SEQ*DM;

    cudaFuncSetAttribute(attn_kernel, cudaFuncAttributeMaxDynamicSharedMemorySize,
                         ATTN_SMEM);

    __half* xh;
    cudaGetSymbolAddress((void**)&xh, g_xh);

    const int NX = BATCH*SEQ*DM, NW = DM*DM;
    cvt_kernel<<<NX/1024, 256>>>(x, xh, NX);
    cvt_w_kernel<<<dim3(NW/1024, 4), 256>>>(wq, wk, wv, wo);

    proj_qkv_kernel<<<dim3(BATCH*SEQ/128, DM/128, 3), 256>>>(bq, bk, bv);
    attn_kernel<<<dim3(SEQ/QT_ROWS, NB), 256, ATTN_SMEM>>>(pm, raw);
    proj_out_kernel<<<dim3(BATCH*SEQ/128, DM/128), 256>>>(bo, out);
}

// round 17
// speedup vs baseline: 1.3656x; 1.1365x over previous
#include <cuda_runtime.h>
#include <cuda_fp16.h>
#include <math.h>

#define BATCH 16
#define SEQ   1024
#define DM    512
#define NH    8
#define HD    64
#define NB    (NH*BATCH)

#define A_LD  40    // proj A tile pitch (halves)
#define B_LD  136   // proj B tile pitch (halves), 128+8
#define T_LD  72    // attn Q/K/V/P tile pitch (halves)
#define KBUF  (64*T_LD)    // K/V buffer stride (halves)
#define PBUF  (128*T_LD)   // P buffer stride (halves)

#define CP16(dst, src) \
    asm volatile("cp.async.cg.shared.global [%0], [%1], 16;" \
                 :: "r"(dst), "l"(src))
#define CPCOMMIT() asm volatile("cp.async.commit_group;")
#define CPWAIT(n)  asm volatile("cp.async.wait_group %0;" :: "n"(n))

// Scratch, fp16 (device globals: allocation-free per harness rules).
__device__ __half g_Q[(size_t)NB*SEQ*HD];   // pre-scaled by 0.125
__device__ __half g_K[(size_t)NB*SEQ*HD];
__device__ __half g_V[(size_t)NB*SEQ*HD];
__device__ __half g_A[(size_t)NB*SEQ*HD];
__device__ __half g_xh[(size_t)BATCH*SEQ*DM];   // fp16 copy of x
__device__ __half g_wh[4][(size_t)DM*DM];       // fp16 wq,wk,wv,wo

__device__ __forceinline__ void st_h4(__half* p, float4 v) {
    __half2 lo = __floats2half2_rn(v.x, v.y);
    __half2 hi = __floats2half2_rn(v.z, v.w);
    uint2 u;
    u.x = *(unsigned int*)&lo;
    u.y = *(unsigned int*)&hi;
    *(uint2*)p = u;
}

__device__ __forceinline__ unsigned su(const void* p) {
    return (unsigned)__cvta_generic_to_shared(p);
}
__device__ __forceinline__ void ldsm4(unsigned& r0, unsigned& r1,
                                      unsigned& r2, unsigned& r3, unsigned a) {
    asm volatile("ldmatrix.sync.aligned.m8n8.x4.shared.b16 {%0,%1,%2,%3},[%4];"
                 : "=r"(r0), "=r"(r1), "=r"(r2), "=r"(r3) : "r"(a));
}
__device__ __forceinline__ void ldsm4t(unsigned& r0, unsigned& r1,
                                       unsigned& r2, unsigned& r3, unsigned a) {
    asm volatile("ldmatrix.sync.aligned.m8n8.x4.trans.shared.b16 {%0,%1,%2,%3},[%4];"
                 : "=r"(r0), "=r"(r1), "=r"(r2), "=r"(r3) : "r"(a));
}
__device__ __forceinline__ void mma_f16(float* d, const unsigned* a,
                                        const unsigned* b) {
    asm volatile("mma.sync.aligned.m16n8k16.row.col.f32.f16.f16.f32 "
                 "{%0,%1,%2,%3},{%4,%5,%6,%7},{%8,%9},{%0,%1,%2,%3};"
                 : "+f"(d[0]), "+f"(d[1]), "+f"(d[2]), "+f"(d[3])
                 : "r"(a[0]), "r"(a[1]), "r"(a[2]), "r"(a[3]),
                   "r"(b[0]), "r"(b[1]));
}

// ---------------------------------------------------------------------------
// fp32 -> fp16 conversion prep kernels
// ---------------------------------------------------------------------------
__global__ __launch_bounds__(256) void cvt_kernel(const float* __restrict__ src,
                                                  __half* __restrict__ dst, int n) {
    int i = (blockIdx.x * 256 + threadIdx.x) * 4;
    if (i < n) st_h4(dst + i, *(const float4*)(src + i));
}
__global__ __launch_bounds__(256) void cvt_w_kernel(
    const float* __restrict__ wq, const float* __restrict__ wk,
    const float* __restrict__ wv, const float* __restrict__ wo) {
    const float* src = (blockIdx.y == 0) ? wq : (blockIdx.y == 1) ? wk
                     : (blockIdx.y == 2) ? wv : wo;
    __half* dst = g_wh[blockIdx.y];
    int i = (blockIdx.x * 256 + threadIdx.x) * 4;
    st_h4(dst + i, *(const float4*)(src + i));
}

// ---------------------------------------------------------------------------
// QKV projection: cp.async 3-stage pipeline, 1 sync/iter, PTX mma,
// register epilogue. Block 128x128, BK=32, 8 warps (4M x 2N) 32x64 each.
// A tile: 2 CP16/thread (rows arow, arow+64). B tile: 2 CP16/thread.
// ---------------------------------------------------------------------------
#define PROJ_SMEM ((3*128*A_LD + 3*32*B_LD)*2)

__global__ __launch_bounds__(256, 2) void proj_qkv_kernel(
    const float* __restrict__ bq, const float* __restrict__ bk,
    const float* __restrict__ bv)
{
    extern __shared__ __half psm[];
    __half* As = psm;                    // 3 x [128][40]
    __half* Bs = psm + 3*128*A_LD;       // 3 x [32][136]

    const float* bias; __half* dst; float oscale;
    const __half* w = g_wh[blockIdx.z];
    if (blockIdx.z == 0)      { bias = bq; dst = g_Q; oscale = 0.125f; }
    else if (blockIdx.z == 1) { bias = bk; dst = g_K; oscale = 1.f; }
    else                      { bias = bv; dst = g_V; oscale = 1.f; }

    const int m0 = blockIdx.x * 128;
    const int n0 = blockIdx.y * 128;
    const int tid = threadIdx.x;
    const int wid = tid >> 5, lane = tid & 31;
    const int wm = wid >> 1, wn = wid & 1;
    const int quad = lane >> 2, lane4 = lane & 3;
    const int sub = lane >> 3, lr8 = lane & 7;
    const int a_r = (sub & 1)*8 + lr8, a_c = (sub >> 1)*8;

    const int arow = tid >> 2,  ac8 = (tid & 3) * 8;    // rows 0..63 (+64 pass)
    const int brow = tid >> 4,  bc8 = (tid & 15) * 8;   // rows 0..15 (+16 pass)

    const unsigned ab0 = su(As), bb0 = su(Bs);

    float o[2][8][4];
    #pragma unroll
    for (int i = 0; i < 2; i++)
        #pragma unroll
        for (int j = 0; j < 8; j++)
            #pragma unroll
            for (int e = 0; e < 4; e++) o[i][j][e] = 0.f;

    float2 bias2[8];
    #pragma unroll
    for (int nf = 0; nf < 8; nf++)
        bias2[nf] = *(const float2*)(bias + n0 + wn*64 + nf*8 + lane4*2);

    // prologue: fill tiles 0 and 1
    #pragma unroll
    for (int T = 0; T < 2; T++) {
        int k0 = T * 32;
        CP16(ab0 + (T*128*A_LD + arow*A_LD + ac8)*2u,
             g_xh + (size_t)(m0 + arow)*DM + k0 + ac8);
        CP16(ab0 + (T*128*A_LD + (arow+64)*A_LD + ac8)*2u,
             g_xh + (size_t)(m0 + arow + 64)*DM + k0 + ac8);
        CP16(bb0 + (T*32*B_LD + brow*B_LD + bc8)*2u,
             w + (size_t)(k0 + brow)*DM + n0 + bc8);
        CP16(bb0 + (T*32*B_LD + (brow+16)*B_LD + bc8)*2u,
             w + (size_t)(k0 + brow + 16)*DM + n0 + bc8);
        CPCOMMIT();
    }
    CPWAIT(1);
    __syncthreads();

    for (int kt = 0; kt < 16; kt++) {
        const int cb = kt % 3;
        const unsigned ab = ab0 + cb*128*A_LD*2u;
        const unsigned bb = bb0 + cb*32*B_LD*2u;

        #pragma unroll
        for (int kf = 0; kf < 2; kf++) {
            unsigned a[2][4], b[8][2];
            #pragma unroll
            for (int mf = 0; mf < 2; mf++)
                ldsm4(a[mf][0], a[mf][1], a[mf][2], a[mf][3],
                      ab + ((wm*32 + mf*16 + a_r)*A_LD + kf*16 + a_c)*2);
            #pragma unroll
            for (int nb = 0; nb < 4; nb++) {
                unsigned r0, r1, r2, r3;
                ldsm4t(r0, r1, r2, r3,
                       bb + ((kf*16 + (sub & 1)*8 + lr8)*B_LD
                             + wn*64 + nb*16 + (sub >> 1)*8)*2);
                b[nb*2+0][0] = r0; b[nb*2+0][1] = r1;
                b[nb*2+1][0] = r2; b[nb*2+1][1] = r3;
            }
            #pragma unroll
            for (int mf = 0; mf < 2; mf++)
                #pragma unroll
                for (int nf = 0; nf < 8; nf++)
                    mma_f16(o[mf][nf], a[mf], b[nf]);
        }

        CPWAIT(0);          // tile kt+1 landed
        __syncthreads();
        if (kt < 14) {      // issue tile kt+2 into buffer (kt+2)%3
            const int nb3 = (kt + 2) % 3;
            const int k0 = (kt + 2) * 32;
            CP16(ab0 + (nb3*128*A_LD + arow*A_LD + ac8)*2u,
                 g_xh + (size_t)(m0 + arow)*DM + k0 + ac8);
            CP16(ab0 + (nb3*128*A_LD + (arow+64)*A_LD + ac8)*2u,
                 g_xh + (size_t)(m0 + arow + 64)*DM + k0 + ac8);
            CP16(bb0 + (nb3*32*B_LD + brow*B_LD + bc8)*2u,
                 w + (size_t)(k0 + brow)*DM + n0 + bc8);
            CP16(bb0 + (nb3*32*B_LD + (brow+16)*B_LD + bc8)*2u,
                 w + (size_t)(k0 + brow + 16)*DM + n0 + bc8);
            CPCOMMIT();
        }
    }

    #pragma unroll
    for (int mf = 0; mf < 2; mf++) {
        int row0 = m0 + wm*32 + mf*16 + quad;
        int b0 = row0 >> 10, s0 = row0 & 1023;
        int row1 = row0 + 8;
        int b1 = row1 >> 10, s1 = row1 & 1023;
        #pragma unroll
        for (int nf = 0; nf < 8; nf++) {
            int col = n0 + wn*64 + nf*8 + lane4*2;
            int h = col >> 6, q0 = col & 63;
            *(__half2*)(dst + (((size_t)(h*BATCH + b0))*SEQ + s0)*HD + q0) =
                __floats2half2_rn((o[mf][nf][0] + bias2[nf].x) * oscale,
                                  (o[mf][nf][1] + bias2[nf].y) * oscale);
            *(__half2*)(dst + (((size_t)(h*BATCH + b1))*SEQ + s1)*HD + q0) =
                __floats2half2_rn((o[mf][nf][2] + bias2[nf].x) * oscale,
                                  (o[mf][nf][3] + bias2[nf].y) * oscale);
        }
    }
}

// ---------------------------------------------------------------------------
// Fused attention: R15 compute, K/V fills via cp.async (3-buffer ring).
// Per iter: S -> softmax/P -> wait0 -> sync -> issue kt+2 -> PV.
// ---------------------------------------------------------------------------
#define QT_ROWS 128
#define ATTN_SMEM ((128*T_LD + 2*PBUF + 6*KBUF)*2 + 2*128*4)

__global__ __launch_bounds__(256, 2) void attn_kernel(const int* __restrict__ pmask,
                                                      float* __restrict__ raw)
{
    extern __shared__ char shb[];
    __half* Qs  = (__half*)shb;                // [128][72]
    __half* Ps  = Qs + 128*T_LD;               // 2 x [128][72]
    __half* Ksb = Ps + 2*PBUF;                 // 3 x [64][72]
    __half* Vsb = Ksb + 3*KBUF;                // 3 x [64][72]
    float*  ls  = (float*)(Vsb + 3*KBUF);      // [2][128]

    const int n  = blockIdx.y;
    const int qt = blockIdx.x;
    const int tid = threadIdx.x;
    const int wid = tid >> 5, lane = tid & 31;
    const int wm = wid >> 1, wn = wid & 1;
    const int quad = lane >> 2, lane4 = lane & 3;
    const int sub = lane >> 3, lr8 = lane & 7;
    const int mb = n >> 3;                     // faithful mask-index mismatch

    const int a_r = (sub & 1)*8 + lr8, a_c = (sub >> 1)*8;
    const int b_r = (sub >> 1)*8 + lr8, b_c = (sub & 1)*8;

    const __half* ksrc = g_K + (size_t)n*SEQ*HD;
    const __half* vsrc = g_V + (size_t)n*SEQ*HD;
    const int*    msrc = pmask + (size_t)mb*SEQ;

    const unsigned qb = su(Qs), pb0 = su(Ps), kbase = su(Ksb), vbase = su(Vsb);

    const int krow = tid >> 3, kc8 = (tid & 7) * 8;   // rows 0..31 (+32 pass)

    const __half* qsrc = g_Q + ((size_t)n*SEQ + qt*128)*HD;
    #pragma unroll
    for (int it = 0; it < 8; it++) {
        int idx = tid + it*256;
        int r = idx >> 4, d0 = (idx & 15) * 4;
        *(uint2*)(Qs + r*T_LD + d0) = *(const uint2*)(qsrc + r*HD + d0);
    }
    #pragma unroll
    for (int T = 0; T < 2; T++) {
        #pragma unroll
        for (int it = 0; it < 2; it++) {
            int t = krow + it*32;
            CP16(kbase + (T*KBUF + t*T_LD + kc8)*2u,
                 ksrc + (size_t)(T*64 + t)*HD + kc8);
            CP16(vbase + (T*KBUF + t*T_LD + kc8)*2u,
                 vsrc + (size_t)(T*64 + t)*HD + kc8);
        }
        CPCOMMIT();
    }
    CPWAIT(1);
    __syncthreads();

    float o[2][4][4];
    #pragma unroll
    for (int i = 0; i < 2; i++)
        #pragma unroll
        for (int j = 0; j < 4; j++)
            #pragma unroll
            for (int e = 0; e < 4; e++) o[i][j][e] = 0.f;
    float rs[2][2] = {{0.f, 0.f}, {0.f, 0.f}};

    const size_t rowg = (size_t)n*SEQ + (size_t)qt*128;

    for (int kt = 0; kt < 16; ++kt) {
        const int cb = kt % 3;
        const int pc = kt & 1;
        const unsigned kb = kbase + cb*KBUF*2;
        const unsigned vb = vbase + cb*KBUF*2;
        const unsigned pbw = pb0 + pc*PBUF*2;
        __half* Pw = Ps + pc*PBUF;

        // ---- S = (Q/8) K^T : warp 32 rows x 32 keys ----
        float s[2][4][4];
        #pragma unroll
        for (int i = 0; i < 2; i++)
            #pragma unroll
            for (int j = 0; j < 4; j++)
                #pragma unroll
                for (int e = 0; e < 4; e++) s[i][j][e] = 0.f;

        #pragma unroll
        for (int kf = 0; kf < 4; kf++) {
            unsigned a[2][4], b[4][2];
            #pragma unroll
            for (int mf = 0; mf < 2; mf++)
                ldsm4(a[mf][0], a[mf][1], a[mf][2], a[mf][3],
                      qb + ((wm*32 + mf*16 + a_r)*T_LD + kf*16 + a_c)*2);
            #pragma unroll
            for (int nb = 0; nb < 2; nb++) {
                unsigned r0, r1, r2, r3;
                ldsm4(r0, r1, r2, r3,
                      kb + ((wn*32 + nb*16 + b_r)*T_LD + kf*16 + b_c)*2);
                b[nb*2+0][0] = r0; b[nb*2+0][1] = r1;
                b[nb*2+1][0] = r2; b[nb*2+1][1] = r3;
            }
            #pragma unroll
            for (int mf = 0; mf < 2; mf++)
                #pragma unroll
                for (int nf = 0; nf < 4; nf++)
                    mma_f16(s[mf][nf], a[mf], b[nf]);
        }

        // ---- raw write (stcs) + mask (cached global) + exp -> P[pc] ----
        #pragma unroll
        for (int mf = 0; mf < 2; mf++) {
            int r0 = wm*32 + mf*16 + quad;
            #pragma unroll
            for (int nf = 0; nf < 4; nf++) {
                int lcol = wn*32 + nf*8 + lane4*2;
                int col  = kt*64 + lcol;
                __stcs((float2*)(raw + (rowg + r0)*SEQ + col),
                       make_float2(s[mf][nf][0], s[mf][nf][1]));
                __stcs((float2*)(raw + (rowg + r0 + 8)*SEQ + col),
                       make_float2(s[mf][nf][2], s[mf][nf][3]));
                int2 mk = *(const int2*)(msrc + col);
                float mx = mk.x ? 1.f : 0.f;
                float my = mk.y ? 1.f : 0.f;
                float p00 = mx * __expf(s[mf][nf][0]);
                float p01 = my * __expf(s[mf][nf][1]);
                float p10 = mx * __expf(s[mf][nf][2]);
                float p11 = my * __expf(s[mf][nf][3]);
                rs[mf][0] += p00 + p01;
                rs[mf][1] += p10 + p11;
                *(__half2*)(Pw + r0*T_LD + lcol)     = __floats2half2_rn(p00, p01);
                *(__half2*)(Pw + (r0+8)*T_LD + lcol) = __floats2half2_rn(p10, p11);
            }
        }

        CPWAIT(0);          // tile kt+1 landed
        __syncthreads();    // P[pc] + K/V[(kt+1)%3] visible

        if (kt < 14) {      // issue tile kt+2 -> buffer (kt+2)%3
            const int nb3 = (kt + 2) % 3;
            #pragma unroll
            for (int it = 0; it < 2; it++) {
                int t = krow + it*32;
                CP16(kbase + (nb3*KBUF + t*T_LD + kc8)*2u,
                     ksrc + (size_t)((kt+2)*64 + t)*HD + kc8);
                CP16(vbase + (nb3*KBUF + t*T_LD + kc8)*2u,
                     vsrc + (size_t)((kt+2)*64 + t)*HD + kc8);
            }
            CPCOMMIT();
        }

        // ---- O += P @ V : warp 32 rows x out cols wn*32..+32, all 64 keys ----
        #pragma unroll
        for (int tf = 0; tf < 4; tf++) {
            unsigned b[4][2];
            #pragma unroll
            for (int nb = 0; nb < 2; nb++) {
                unsigned r0, r1, r2, r3;
                ldsm4t(r0, r1, r2, r3,
                       vb + ((tf*16 + (sub & 1)*8 + lr8)*T_LD
                             + wn*32 + nb*16 + (sub >> 1)*8)*2);
                b[nb*2+0][0] = r0; b[nb*2+0][1] = r1;
                b[nb*2+1][0] = r2; b[nb*2+1][1] = r3;
            }
            #pragma unroll
            for (int mf = 0; mf < 2; mf++) {
                unsigned pa[4];
                ldsm4(pa[0], pa[1], pa[2], pa[3],
                      pbw + ((wm*32 + mf*16 + a_r)*T_LD + tf*16 + a_c)*2);
                #pragma unroll
                for (int nf = 0; nf < 4; nf++)
                    mma_f16(o[mf][nf], pa, b[nf]);
            }
        }
    }

    // ---- epilogue ----
    #pragma unroll
    for (int mf = 0; mf < 2; mf++)
        #pragma unroll
        for (int rg = 0; rg < 2; rg++) {
            rs[mf][rg] += __shfl_xor_sync(0xffffffffu, rs[mf][rg], 1);
            rs[mf][rg] += __shfl_xor_sync(0xffffffffu, rs[mf][rg], 2);
        }
    if (lane4 == 0) {
        #pragma unroll
        for (int mf = 0; mf < 2; mf++) {
            int r0 = wm*32 + mf*16 + quad;
            ls[wn*128 + r0]     = rs[mf][0];
            ls[wn*128 + r0 + 8] = rs[mf][1];
        }
    }
    __syncthreads();

    #pragma unroll
    for (int mf = 0; mf < 2; mf++) {
        int r0 = wm*32 + mf*16 + quad;
        float inv0 = 1.f / (ls[r0] + ls[128 + r0]);
        float inv1 = 1.f / (ls[r0 + 8] + ls[128 + r0 + 8]);
        __half* adst = g_A + (rowg + r0)*HD;
        #pragma unroll
        for (int nf = 0; nf < 4; nf++) {
            int col = wn*32 + nf*8 + lane4*2;
            *(__half2*)(adst + col) =
                __floats2half2_rn(o[mf][nf][0]*inv0, o[mf][nf][1]*inv0);
            *(__half2*)(adst + 8*HD + col) =
                __floats2half2_rn(o[mf][nf][2]*inv1, o[mf][nf][3]*inv1);
        }
    }
}

// ---------------------------------------------------------------------------
// Output projection: cp.async 3-stage pipeline, gathered A from g_A.
// ---------------------------------------------------------------------------
__global__ __launch_bounds__(256, 2) void proj_out_kernel(
    const float* __restrict__ bo, float* __restrict__ out)
{
    extern __shared__ __half psm[];
    __half* As = psm;
    __half* Bs = psm + 3*128*A_LD;

    const __half* w = g_wh[3];
    const int m0 = blockIdx.x * 128;
    const int n0 = blockIdx.y * 128;
    const int tid = threadIdx.x;
    const int wid = tid >> 5, lane = tid & 31;
    const int wm = wid >> 1, wn = wid & 1;
    const int quad = lane >> 2, lane4 = lane & 3;
    const int sub = lane >> 3, lr8 = lane & 7;
    const int a_r = (sub & 1)*8 + lr8, a_c = (sub >> 1)*8;

    const int arow = tid >> 2,  ac8 = (tid & 3) * 8;
    const int brow = tid >> 4,  bc8 = (tid & 15) * 8;
    const int rowA0 = m0 + arow;
    const int bA0 = rowA0 >> 10, sA0 = rowA0 & 1023;
    const int rowA1 = rowA0 + 64;
    const int bA1 = rowA1 >> 10, sA1 = rowA1 & 1023;

    const unsigned ab0 = su(As), bb0 = su(Bs);

    float o[2][8][4];
    #pragma unroll
    for (int i = 0; i < 2; i++)
        #pragma unroll
        for (int j = 0; j < 8; j++)
            #pragma unroll
            for (int e = 0; e < 4; e++) o[i][j][e] = 0.f;

    float2 bias2[8];
    #pragma unroll
    for (int nf = 0; nf < 8; nf++)
        bias2[nf] = *(const float2*)(bo + n0 + wn*64 + nf*8 + lane4*2);

    #pragma unroll
    for (int T = 0; T < 2; T++) {
        int k0 = T * 32;
        int h = k0 >> 6, v0 = k0 & 63;
        CP16(ab0 + (T*128*A_LD + arow*A_LD + ac8)*2u,
             g_A + (((size_t)(h*BATCH + bA0))*SEQ + sA0)*HD + v0 + ac8);
        CP16(ab0 + (T*128*A_LD + (arow+64)*A_LD + ac8)*2u,
             g_A + (((size_t)(h*BATCH + bA1))*SEQ + sA1)*HD + v0 + ac8);
        CP16(bb0 + (T*32*B_LD + brow*B_LD + bc8)*2u,
             w + (size_t)(k0 + brow)*DM + n0 + bc8);
        CP16(bb0 + (T*32*B_LD + (brow+16)*B_LD + bc8)*2u,
             w + (size_t)(k0 + brow + 16)*DM + n0 + bc8);
        CPCOMMIT();
    }
    CPWAIT(1);
    __syncthreads();

    for (int kt = 0; kt < 16; kt++) {
        const int cb = kt % 3;
        const unsigned ab = ab0 + cb*128*A_LD*2u;
        const unsigned bb = bb0 + cb*32*B_LD*2u;

        #pragma unroll
        for (int kf = 0; kf < 2; kf++) {
            unsigned a[2][4], b[8][2];
            #pragma unroll
            for (int mf = 0; mf < 2; mf++)
                ldsm4(a[mf][0], a[mf][1], a[mf][2], a[mf][3],
                      ab + ((wm*32 + mf*16 + a_r)*A_LD + kf*16 + a_c)*2);
            #pragma unroll
            for (int nb = 0; nb < 4; nb++) {
                unsigned r0, r1, r2, r3;
                ldsm4t(r0, r1, r2, r3,
                       bb + ((kf*16 + (sub & 1)*8 + lr8)*B_LD
                             + wn*64 + nb*16 + (sub >> 1)*8)*2);
                b[nb*2+0][0] = r0; b[nb*2+0][1] = r1;
                b[nb*2+1][0] = r2; b[nb*2+1][1] = r3;
            }
            #pragma unroll
            for (int mf = 0; mf < 2; mf++)
                #pragma unroll
                for (int nf = 0; nf < 8; nf++)
                    mma_f16(o[mf][nf], a[mf], b[nf]);
        }

        CPWAIT(0);
        __syncthreads();
        if (kt < 14) {
            const int nb3 = (kt + 2) % 3;
            const int k0 = (kt + 2) * 32;
            int h = k0 >> 6, v0 = k0 & 63;
            CP16(ab0 + (nb3*128*A_LD + arow*A_LD + ac8)*2u,
                 g_A + (((size_t)(h*BATCH + bA0))*SEQ + sA0)*HD + v0 + ac8);
            CP16(ab0 + (nb3*128*A_LD + (arow+64)*A_LD + ac8)*2u,
                 g_A + (((size_t)(h*BATCH + bA1))*SEQ + sA1)*HD + v0 + ac8);
            CP16(bb0 + (nb3*32*B_LD + brow*B_LD + bc8)*2u,
                 w + (size_t)(k0 + brow)*DM + n0 + bc8);
            CP16(bb0 + (nb3*32*B_LD + (brow+16)*B_LD + bc8)*2u,
                 w + (size_t)(k0 + brow + 16)*DM + n0 + bc8);
            CPCOMMIT();
        }
    }

    #pragma unroll
    for (int mf = 0; mf < 2; mf++) {
        int row0 = m0 + wm*32 + mf*16 + quad;
        #pragma unroll
        for (int nf = 0; nf < 8; nf++) {
            int col = n0 + wn*64 + nf*8 + lane4*2;
            __stcs((float2*)(out + (size_t)row0*DM + col),
                   make_float2(o[mf][nf][0] + bias2[nf].x,
                               o[mf][nf][1] + bias2[nf].y));
            __stcs((float2*)(out + (size_t)(row0+8)*DM + col),
                   make_float2(o[mf][nf][2] + bias2[nf].x,
                               o[mf][nf][3] + bias2[nf].y));
        }
    }
}

// ---------------------------------------------------------------------------
extern "C" void kernel_launch(void* const* d_in, const int* in_sizes, int n_in,
                              void* d_out, int out_size)
{
    (void)in_sizes; (void)n_in; (void)out_size;
    const float* x  = (const float*)d_in[0];
    const int*   pm = (const int*)  d_in[1];
    const float* wq = (const float*)d_in[2];
    const float* bq = (const float*)d_in[3];
    const float* wk = (const float*)d_in[4];
    const float* bk = (const float*)d_in[5];
    const float* wv = (const float*)d_in[6];
    const float* bv = (const float*)d_in[7];
    const float* wo = (const float*)d_in[8];
    const float* bo = (const float*)d_in[9];

    float* out = (float*)d_out;
    float* raw = out + (size_t)BATCH*SEQ*DM;

    cudaFuncSetAttribute(attn_kernel, cudaFuncAttributeMaxDynamicSharedMemorySize,
                         ATTN_SMEM);
    cudaFuncSetAttribute(proj_qkv_kernel, cudaFuncAttributeMaxDynamicSharedMemorySize,
                         PROJ_SMEM);
    cudaFuncSetAttribute(proj_out_kernel, cudaFuncAttributeMaxDynamicSharedMemorySize,
                         PROJ_SMEM);

    __half* xh;
    cudaGetSymbolAddress((void**)&xh, g_xh);

    const int NX = BATCH*SEQ*DM, NW = DM*DM;
    cvt_kernel<<<NX/1024, 256>>>(x, xh, NX);
    cvt_w_kernel<<<dim3(NW/1024, 4), 256>>>(wq, wk, wv, wo);

    proj_qkv_kernel<<<dim3(BATCH*SEQ/128, DM/128, 3), 256, PROJ_SMEM>>>(bq, bk, bv);
    attn_kernel<<<dim3(SEQ/QT_ROWS, NB), 256, ATTN_SMEM>>>(pm, raw);
    proj_out_kernel<<<dim3(BATCH*SEQ/128, DM/128), 256, PROJ_SMEM>>>(bo, out);
}